// round 1
// baseline (speedup 1.0000x reference)
#include <cuda_runtime.h>
#include <math.h>

#define T_DIM 4096
#define C_DIM 768
#define H_DIM 12
#define D_DIM 64
#define C3_DIM 2304

// Scratch (allocation-free rule: __device__ globals)
__device__ float g_q[H_DIM * T_DIM * D_DIM];
__device__ float g_k[H_DIM * T_DIM * D_DIM];
__device__ float g_v[H_DIM * T_DIM * D_DIM];
__device__ float g_y[T_DIM * C_DIM];

// ---------------------------------------------------------------------------
// Kernel 1: QKV GEMM  x[4096,768] @ W[768,2304] + b  -> scatter to Q/K/V [H,T,D]
// 64x64 tile, 256 threads, 4x4 micro-tile, K-chunk 16.
// ---------------------------------------------------------------------------
__global__ void qkv_gemm_kernel(const float* __restrict__ x,
                                const float* __restrict__ W,
                                const float* __restrict__ bias) {
    __shared__ float As[16][65];   // As[k][m]
    __shared__ float Bs[16][65];   // Bs[k][n]

    const int m0 = blockIdx.y * 64;
    const int n0 = blockIdx.x * 64;
    const int tid = threadIdx.x;
    const int tx = tid & 15;
    const int ty = tid >> 4;

    float acc[4][4] = {};

    for (int k0 = 0; k0 < C_DIM; k0 += 16) {
        // load x tile (transposed into As[k][m])
        #pragma unroll
        for (int i = tid; i < 1024; i += 256) {
            int m = i >> 4, k = i & 15;
            As[k][m] = x[(m0 + m) * C_DIM + k0 + k];
        }
        // load W tile
        #pragma unroll
        for (int i = tid; i < 1024; i += 256) {
            int kk = i >> 6, j = i & 63;
            Bs[kk][j] = W[(k0 + kk) * C3_DIM + n0 + j];
        }
        __syncthreads();

        #pragma unroll
        for (int kk = 0; kk < 16; kk++) {
            float a[4], b[4];
            #pragma unroll
            for (int i = 0; i < 4; i++) a[i] = As[kk][ty * 4 + i];
            #pragma unroll
            for (int j = 0; j < 4; j++) b[j] = Bs[kk][tx * 4 + j];
            #pragma unroll
            for (int i = 0; i < 4; i++)
                #pragma unroll
                for (int j = 0; j < 4; j++)
                    acc[i][j] += a[i] * b[j];
        }
        __syncthreads();
    }

    // epilogue: bias + scatter.  A 64-wide tile never crosses a Q/K/V section
    // boundary (768 % 64 == 0) nor a head boundary (64 == D).
    #pragma unroll
    for (int i = 0; i < 4; i++) {
        int t = m0 + ty * 4 + i;
        #pragma unroll
        for (int j = 0; j < 4; j++) {
            int f = n0 + tx * 4 + j;
            float v = acc[i][j] + bias[f];
            int sec = f / C_DIM;
            int c = f - sec * C_DIM;
            int h = c / D_DIM;
            int d = c - h * D_DIM;
            float* dst = (sec == 0) ? g_q : (sec == 1) ? g_k : g_v;
            dst[(h * T_DIM + t) * D_DIM + d] = v;
        }
    }
}

// ---------------------------------------------------------------------------
// Kernel 2: causal flash attention. One CTA per (query-block of 64, head).
// Online softmax, K/V streamed through SMEM, blocks beyond the diagonal skipped.
// ---------------------------------------------------------------------------
__global__ void attn_kernel() {
    extern __shared__ float sm[];
    float* Qs = sm;                 // 64*65
    float* Ks = Qs + 64 * 65;       // 64*65  (Ks[col][kd])
    float* Vs = Ks + 64 * 65;       // 64*65  (Vs[k][col])
    float* Ss = Vs + 64 * 65;       // 64*65

    __shared__ float m_sh[64], l_sh[64], corr_sh[64];
    __shared__ float red[64][4];

    const int h = blockIdx.y;
    const int qb = blockIdx.x;
    const int tid = threadIdx.x;
    const int tx = tid & 15;
    const int ty = tid >> 4;
    const int rr = tid >> 2;        // row for softmax bookkeeping
    const int pp = tid & 3;         // 16-col slice within row
    const float scale = 0.125f;     // 1/sqrt(64)

    // load Q tile
    const float* Qg = g_q + (h * T_DIM + qb * 64) * D_DIM;
    #pragma unroll
    for (int i = tid; i < 4096; i += 256) {
        int r = i >> 6, d = i & 63;
        Qs[r * 65 + d] = Qg[r * 64 + d];
    }
    if (tid < 64) { m_sh[tid] = -1e30f; l_sh[tid] = 0.0f; }

    float o[4][4] = {};
    __syncthreads();

    for (int jb = 0; jb <= qb; jb++) {
        __syncthreads();   // guard prior iteration's Vs/Ss reads
        const float* Kg = g_k + (h * T_DIM + jb * 64) * D_DIM;
        const float* Vg = g_v + (h * T_DIM + jb * 64) * D_DIM;
        #pragma unroll
        for (int i = tid; i < 4096; i += 256) {
            int r = i >> 6, d = i & 63;
            Ks[r * 65 + d] = Kg[r * 64 + d];
            Vs[r * 65 + d] = Vg[r * 64 + d];
        }
        __syncthreads();

        // S = Q K^T
        float s[4][4] = {};
        #pragma unroll 8
        for (int kd = 0; kd < 64; kd++) {
            float a[4], b[4];
            #pragma unroll
            for (int i = 0; i < 4; i++) a[i] = Qs[(ty * 4 + i) * 65 + kd];
            #pragma unroll
            for (int j = 0; j < 4; j++) b[j] = Ks[(tx * 4 + j) * 65 + kd];
            #pragma unroll
            for (int i = 0; i < 4; i++)
                #pragma unroll
                for (int j = 0; j < 4; j++)
                    s[i][j] += a[i] * b[j];
        }

        // scale + causal mask + stage to SMEM
        #pragma unroll
        for (int i = 0; i < 4; i++) {
            int qrow = qb * 64 + ty * 4 + i;
            #pragma unroll
            for (int j = 0; j < 4; j++) {
                int kcol = jb * 64 + tx * 4 + j;
                float val = s[i][j] * scale;
                if (kcol > qrow) val = -1e30f;
                Ss[(ty * 4 + i) * 65 + tx * 4 + j] = val;
            }
        }
        __syncthreads();

        // row max (4 threads per row, 16 cols each)
        float lm = -1e30f;
        #pragma unroll
        for (int c = pp * 16; c < pp * 16 + 16; c++)
            lm = fmaxf(lm, Ss[rr * 65 + c]);
        red[rr][pp] = lm;
        __syncthreads();
        if (pp == 0) {
            float mn = fmaxf(fmaxf(red[rr][0], red[rr][1]),
                             fmaxf(red[rr][2], red[rr][3]));
            mn = fmaxf(mn, m_sh[rr]);
            corr_sh[rr] = __expf(m_sh[rr] - mn);
            m_sh[rr] = mn;
        }
        __syncthreads();

        // exponentiate + partial sums
        float mnew = m_sh[rr];
        float psum = 0.0f;
        #pragma unroll
        for (int c = pp * 16; c < pp * 16 + 16; c++) {
            float e = __expf(Ss[rr * 65 + c] - mnew);
            Ss[rr * 65 + c] = e;
            psum += e;
        }
        red[rr][pp] = psum;
        __syncthreads();
        if (pp == 0)
            l_sh[rr] = l_sh[rr] * corr_sh[rr] +
                       red[rr][0] + red[rr][1] + red[rr][2] + red[rr][3];

        // O = O*corr + P V
        float cr[4];
        #pragma unroll
        for (int i = 0; i < 4; i++) cr[i] = corr_sh[ty * 4 + i];
        #pragma unroll
        for (int i = 0; i < 4; i++)
            #pragma unroll
            for (int j = 0; j < 4; j++)
                o[i][j] *= cr[i];

        #pragma unroll 8
        for (int k = 0; k < 64; k++) {
            float p[4], v[4];
            #pragma unroll
            for (int i = 0; i < 4; i++) p[i] = Ss[(ty * 4 + i) * 65 + k];
            #pragma unroll
            for (int j = 0; j < 4; j++) v[j] = Vs[k * 65 + tx * 4 + j];
            #pragma unroll
            for (int i = 0; i < 4; i++)
                #pragma unroll
                for (int j = 0; j < 4; j++)
                    o[i][j] += p[i] * v[j];
        }
    }
    __syncthreads();   // make final l_sh (written by pp==0) visible

    // epilogue: normalize, write y in [T, C] layout
    #pragma unroll
    for (int i = 0; i < 4; i++) {
        int trow = qb * 64 + ty * 4 + i;
        float inv_l = 1.0f / l_sh[ty * 4 + i];
        #pragma unroll
        for (int j = 0; j < 4; j++)
            g_y[trow * C_DIM + h * D_DIM + tx * 4 + j] = o[i][j] * inv_l;
    }
}

// ---------------------------------------------------------------------------
// Kernel 3: projection GEMM  y[4096,768] @ Wp[768,768] + b -> out
// ---------------------------------------------------------------------------
__global__ void proj_gemm_kernel(const float* __restrict__ W,
                                 const float* __restrict__ bias,
                                 float* __restrict__ out) {
    __shared__ float As[16][65];
    __shared__ float Bs[16][65];

    const int m0 = blockIdx.y * 64;
    const int n0 = blockIdx.x * 64;
    const int tid = threadIdx.x;
    const int tx = tid & 15;
    const int ty = tid >> 4;

    float acc[4][4] = {};

    for (int k0 = 0; k0 < C_DIM; k0 += 16) {
        #pragma unroll
        for (int i = tid; i < 1024; i += 256) {
            int m = i >> 4, k = i & 15;
            As[k][m] = g_y[(m0 + m) * C_DIM + k0 + k];
        }
        #pragma unroll
        for (int i = tid; i < 1024; i += 256) {
            int kk = i >> 6, j = i & 63;
            Bs[kk][j] = W[(k0 + kk) * C_DIM + n0 + j];
        }
        __syncthreads();

        #pragma unroll
        for (int kk = 0; kk < 16; kk++) {
            float a[4], b[4];
            #pragma unroll
            for (int i = 0; i < 4; i++) a[i] = As[kk][ty * 4 + i];
            #pragma unroll
            for (int j = 0; j < 4; j++) b[j] = Bs[kk][tx * 4 + j];
            #pragma unroll
            for (int i = 0; i < 4; i++)
                #pragma unroll
                for (int j = 0; j < 4; j++)
                    acc[i][j] += a[i] * b[j];
        }
        __syncthreads();
    }

    #pragma unroll
    for (int i = 0; i < 4; i++) {
        int t = m0 + ty * 4 + i;
        #pragma unroll
        for (int j = 0; j < 4; j++) {
            int f = n0 + tx * 4 + j;
            out[t * C_DIM + f] = acc[i][j] + bias[f];
        }
    }
}

// ---------------------------------------------------------------------------
extern "C" void kernel_launch(void* const* d_in, const int* in_sizes, int n_in,
                              void* d_out, int out_size) {
    const float* x      = (const float*)d_in[0];
    // d_in[1] is the causal mask — applied analytically in attn_kernel.
    const float* W_qkv  = (const float*)d_in[2];
    const float* b_qkv  = (const float*)d_in[3];
    const float* W_proj = (const float*)d_in[4];
    const float* b_proj = (const float*)d_in[5];
    float* out = (float*)d_out;

    // QKV GEMM: M=4096, N=2304
    {
        dim3 grid(C3_DIM / 64, T_DIM / 64);
        qkv_gemm_kernel<<<grid, 256>>>(x, W_qkv, b_qkv);
    }

    // Attention: (query blocks, heads)
    {
        static int smem_set = 0;
        const int smem_bytes = 4 * 64 * 65 * (int)sizeof(float);
        if (!smem_set) {
            cudaFuncSetAttribute(attn_kernel,
                                 cudaFuncAttributeMaxDynamicSharedMemorySize,
                                 smem_bytes);
            smem_set = 1;
        }
        dim3 grid(T_DIM / 64, H_DIM);
        attn_kernel<<<grid, 256, smem_bytes>>>();
    }

    // Projection GEMM: M=4096, N=768
    {
        dim3 grid(C_DIM / 64, T_DIM / 64);
        proj_gemm_kernel<<<grid, 256>>>(W_proj, b_proj, out);
    }
}

// round 2
// speedup vs baseline: 1.4241x; 1.4241x over previous
#include <cuda_runtime.h>
#include <math.h>

#define T_DIM 4096
#define C_DIM 768
#define H_DIM 12
#define D_DIM 64
#define C3_DIM 2304

typedef unsigned long long ull;

// Scratch (allocation-free rule: __device__ globals)
__device__ float g_q[H_DIM * T_DIM * D_DIM];
__device__ float g_k[H_DIM * T_DIM * D_DIM];
__device__ float g_v[H_DIM * T_DIM * D_DIM];
__device__ float g_y[T_DIM * C_DIM];

// ---- f32x2 packed helpers -------------------------------------------------
#define FMA2(c, a, b) asm("fma.rn.f32x2 %0, %1, %2, %0;" : "+l"(c) : "l"(a), "l"(b))
#define MUL2(d, a, b) asm("mul.rn.f32x2 %0, %1, %2;" : "=l"(d) : "l"(a), "l"(b))

__device__ __forceinline__ ull dup2(float x) {
    ull r; asm("mov.b64 %0, {%1, %1};" : "=l"(r) : "f"(x)); return r;
}
__device__ __forceinline__ float2 unpack2(ull u) {
    float2 r; asm("mov.b64 {%0, %1}, %2;" : "=f"(r.x), "=f"(r.y) : "l"(u)); return r;
}

// MUFU-free exp: exp(x) = 2^(x*log2e), clamped so masked (-1e30) -> ~0.
__device__ __forceinline__ float fast_exp(float x) {
    float t = fmaxf(x * 1.4426950408889634f, -126.0f);
    int   n = __float2int_rn(t);
    float r = t - (float)n;
    float p = 1.3333558146428443e-3f;
    p = fmaf(p, r, 9.6181291976353663e-3f);
    p = fmaf(p, r, 5.5504108664823058e-2f);
    p = fmaf(p, r, 2.4022650695910071e-1f);
    p = fmaf(p, r, 6.9314718055994531e-1f);
    p = fmaf(p, r, 1.0f);
    return p * __int_as_float((n + 127) << 23);
}

// ---------------------------------------------------------------------------
// GEMM mainloop: 128x128 tile, 256 threads, 8 rows x 4 col-pairs per thread,
// f32x2 accumulation packed along N. Double-buffered SMEM, 1 sync per chunk.
// Thread (tx=tid&15, ty=tid>>4): rows 8*ty..+7, col pairs {2tx+32j, +1}.
// ---------------------------------------------------------------------------
__device__ __forceinline__ void gemm_tile(const float* __restrict__ A, int lda,
                                          const float* __restrict__ B, int ldb,
                                          int m0, int n0, int kdim,
                                          ull acc[8][4]) {
    __shared__ float As[2][8][132];   // [k][m] transposed
    __shared__ float Bs[2][8][132];   // [k][n]

    const int tid = threadIdx.x;
    const int tx = tid & 15, ty = tid >> 4;
    const int am = tid >> 1, ak = (tid & 1) * 4;
    const int bk = tid >> 5, bn = (tid & 31) * 4;

    // prologue: stage chunk 0
    {
        float4 av = *(const float4*)&A[(m0 + am) * lda + ak];
        As[0][ak + 0][am] = av.x; As[0][ak + 1][am] = av.y;
        As[0][ak + 2][am] = av.z; As[0][ak + 3][am] = av.w;
        *(float4*)&Bs[0][bk][bn] = *(const float4*)&B[bk * ldb + n0 + bn];
    }
    __syncthreads();

    const int nch = kdim >> 3;
    for (int c = 0; c < nch; c++) {
        const int buf = c & 1;
        const bool more = (c + 1 < nch);
        float4 av, bv;
        if (more) {
            int k0 = (c + 1) * 8;
            av = *(const float4*)&A[(m0 + am) * lda + k0 + ak];
            bv = *(const float4*)&B[(k0 + bk) * ldb + n0 + bn];
        }
        #pragma unroll
        for (int kk = 0; kk < 8; kk++) {
            float4 a0 = *(const float4*)&As[buf][kk][8 * ty];
            float4 a1 = *(const float4*)&As[buf][kk][8 * ty + 4];
            ull bp[4];
            #pragma unroll
            for (int j = 0; j < 4; j++)
                bp[j] = *(const ull*)&Bs[buf][kk][2 * tx + 32 * j];
            ull ad[8];
            ad[0] = dup2(a0.x); ad[1] = dup2(a0.y);
            ad[2] = dup2(a0.z); ad[3] = dup2(a0.w);
            ad[4] = dup2(a1.x); ad[5] = dup2(a1.y);
            ad[6] = dup2(a1.z); ad[7] = dup2(a1.w);
            #pragma unroll
            for (int i = 0; i < 8; i++)
                #pragma unroll
                for (int j = 0; j < 4; j++)
                    FMA2(acc[i][j], ad[i], bp[j]);
        }
        if (more) {
            const int nb = (c + 1) & 1;
            As[nb][ak + 0][am] = av.x; As[nb][ak + 1][am] = av.y;
            As[nb][ak + 2][am] = av.z; As[nb][ak + 3][am] = av.w;
            *(float4*)&Bs[nb][bk][bn] = bv;
        }
        __syncthreads();
    }
}

// ---------------------------------------------------------------------------
// Kernel 1: QKV GEMM + bias + scatter to [H,T,D] Q/K/V
// ---------------------------------------------------------------------------
__global__ __launch_bounds__(256, 1)
void qkv_gemm_kernel(const float* __restrict__ x,
                     const float* __restrict__ W,
                     const float* __restrict__ bias) {
    const int m0 = blockIdx.y * 128;
    const int n0 = blockIdx.x * 128;
    const int tx = threadIdx.x & 15, ty = threadIdx.x >> 4;

    ull acc[8][4];
    #pragma unroll
    for (int i = 0; i < 8; i++)
        #pragma unroll
        for (int j = 0; j < 4; j++) acc[i][j] = 0ull;

    gemm_tile(x, C_DIM, W, C3_DIM, m0, n0, C_DIM, acc);

    #pragma unroll
    for (int j = 0; j < 4; j++) {
        const int f = n0 + 2 * tx + 32 * j;
        const float b0 = bias[f], b1 = bias[f + 1];
        const int sec = f / C_DIM;
        const int cc = f - sec * C_DIM;
        const int h = cc >> 6, d = cc & 63;
        float* dst = (sec == 0) ? g_q : (sec == 1) ? g_k : g_v;
        #pragma unroll
        for (int i = 0; i < 8; i++) {
            const int t = m0 + 8 * ty + i;
            float2 r = unpack2(acc[i][j]);
            r.x += b0; r.y += b1;
            *(float2*)&dst[(h * T_DIM + t) * D_DIM + d] = r;
        }
    }
}

// ---------------------------------------------------------------------------
// Kernel 2: causal flash attention. Br=128, Bc=64, 256 threads.
// S packed along d (lane-sum at end); O packed along output cols.
// MUFU-free exp; shuffle-based row reductions (no SMEM round trips).
// ---------------------------------------------------------------------------
#define AP 68   // padded row stride (words) for attention SMEM tiles

__global__ __launch_bounds__(256, 1)
void attn_kernel() {
    extern __shared__ float sm[];
    float* Qs = sm;                       // 128 x AP
    float* Ks = Qs + 128 * AP;            // 64 x AP
    float* Vs = Ks + 64 * AP;             // 64 x AP
    float* Ss = Vs + 64 * AP;             // 128 x AP

    const int h  = blockIdx.y;
    const int qb = gridDim.x - 1 - blockIdx.x;   // heavy blocks first
    const int tid = threadIdx.x;
    const int tx = tid & 15, ty = tid >> 4;
    const int sr = tid >> 4;            // staging: 16 rows per pass
    const int sd = (tid & 15) * 4;

    // stage Q (pre-scaled by 1/sqrt(D))
    const float* Qg = g_q + (h * T_DIM + qb * 128) * D_DIM;
    #pragma unroll
    for (int p = 0; p < 8; p++) {
        int r = sr + p * 16;
        float4 v = *(const float4*)&Qg[r * D_DIM + sd];
        v.x *= 0.125f; v.y *= 0.125f; v.z *= 0.125f; v.w *= 0.125f;
        *(float4*)&Qs[r * AP + sd] = v;
    }

    float m_i[8], l_i[8];
    ull o2[8][2];
    #pragma unroll
    for (int i = 0; i < 8; i++) {
        m_i[i] = -1e30f; l_i[i] = 0.0f; o2[i][0] = 0ull; o2[i][1] = 0ull;
    }

    const int jend = 2 * qb + 1;
    for (int jb = 0; jb <= jend; jb++) {
        __syncthreads();   // prev-iter PV reads done (and Q staged, iter 0)
        const float* Kg = g_k + (h * T_DIM + jb * 64) * D_DIM;
        const float* Vg = g_v + (h * T_DIM + jb * 64) * D_DIM;
        #pragma unroll
        for (int p = 0; p < 4; p++) {
            int r = sr + p * 16;
            *(float4*)&Ks[r * AP + sd] = *(const float4*)&Kg[r * D_DIM + sd];
            *(float4*)&Vs[r * AP + sd] = *(const float4*)&Vg[r * D_DIM + sd];
        }
        __syncthreads();

        // ---- S = Q K^T, f32x2 packed along d; cols tx + 16j ----
        ull sa[8][4];
        #pragma unroll
        for (int i = 0; i < 8; i++)
            #pragma unroll
            for (int j = 0; j < 4; j++) sa[i][j] = 0ull;

        #pragma unroll 4
        for (int d = 0; d < 64; d += 4) {
            ulonglong2 b4[4];
            #pragma unroll
            for (int j = 0; j < 4; j++)
                b4[j] = *(const ulonglong2*)&Ks[(tx + 16 * j) * AP + d];
            #pragma unroll
            for (int i = 0; i < 8; i++) {
                ulonglong2 a4 = *(const ulonglong2*)&Qs[(8 * ty + i) * AP + d];
                #pragma unroll
                for (int j = 0; j < 4; j++) {
                    FMA2(sa[i][j], a4.x, b4[j].x);
                    FMA2(sa[i][j], a4.y, b4[j].y);
                }
            }
        }
        float s[8][4];
        #pragma unroll
        for (int i = 0; i < 8; i++)
            #pragma unroll
            for (int j = 0; j < 4; j++) {
                float2 v = unpack2(sa[i][j]);
                s[i][j] = v.x + v.y;
            }

        // causal mask (only the last two key blocks can be masked)
        if (jb >= 2 * qb) {
            #pragma unroll
            for (int i = 0; i < 8; i++) {
                const int qrow = qb * 128 + 8 * ty + i;
                #pragma unroll
                for (int j = 0; j < 4; j++)
                    if (jb * 64 + tx + 16 * j > qrow) s[i][j] = -1e30f;
            }
        }

        // ---- online softmax (register + shuffle, 16-lane groups) ----
        #pragma unroll
        for (int i = 0; i < 8; i++) {
            float bm = fmaxf(fmaxf(s[i][0], s[i][1]), fmaxf(s[i][2], s[i][3]));
            bm = fmaxf(bm, __shfl_xor_sync(0xffffffffu, bm, 1));
            bm = fmaxf(bm, __shfl_xor_sync(0xffffffffu, bm, 2));
            bm = fmaxf(bm, __shfl_xor_sync(0xffffffffu, bm, 4));
            bm = fmaxf(bm, __shfl_xor_sync(0xffffffffu, bm, 8));
            const float mn = fmaxf(m_i[i], bm);
            const float corr = fast_exp(m_i[i] - mn);
            m_i[i] = mn;
            float rs = 0.0f;
            #pragma unroll
            for (int j = 0; j < 4; j++) {
                s[i][j] = fast_exp(s[i][j] - mn);
                rs += s[i][j];
            }
            rs += __shfl_xor_sync(0xffffffffu, rs, 1);
            rs += __shfl_xor_sync(0xffffffffu, rs, 2);
            rs += __shfl_xor_sync(0xffffffffu, rs, 4);
            rs += __shfl_xor_sync(0xffffffffu, rs, 8);
            l_i[i] = l_i[i] * corr + rs;
            const ull cd = dup2(corr);
            MUL2(o2[i][0], o2[i][0], cd);
            MUL2(o2[i][1], o2[i][1], cd);
            const int rb = (8 * ty + i) * AP + tx;
            Ss[rb +  0] = s[i][0];
            Ss[rb + 16] = s[i][1];
            Ss[rb + 32] = s[i][2];
            Ss[rb + 48] = s[i][3];
        }
        __syncthreads();

        // ---- O += P V, f32x2 packed along cols {2tx, 2tx+32} ----
        #pragma unroll 2
        for (int k = 0; k < 64; k += 4) {
            ull bv0[4], bv1[4];
            #pragma unroll
            for (int kk = 0; kk < 4; kk++) {
                bv0[kk] = *(const ull*)&Vs[(k + kk) * AP + 2 * tx];
                bv1[kk] = *(const ull*)&Vs[(k + kk) * AP + 2 * tx + 32];
            }
            #pragma unroll
            for (int i = 0; i < 8; i++) {
                float4 pv = *(const float4*)&Ss[(8 * ty + i) * AP + k];
                ull pd;
                pd = dup2(pv.x); FMA2(o2[i][0], pd, bv0[0]); FMA2(o2[i][1], pd, bv1[0]);
                pd = dup2(pv.y); FMA2(o2[i][0], pd, bv0[1]); FMA2(o2[i][1], pd, bv1[1]);
                pd = dup2(pv.z); FMA2(o2[i][0], pd, bv0[2]); FMA2(o2[i][1], pd, bv1[2]);
                pd = dup2(pv.w); FMA2(o2[i][0], pd, bv0[3]); FMA2(o2[i][1], pd, bv1[3]);
            }
        }
    }

    // epilogue: normalize + write y [T, C]
    #pragma unroll
    for (int i = 0; i < 8; i++) {
        const float inv = 1.0f / l_i[i];
        float2 p0 = unpack2(o2[i][0]); p0.x *= inv; p0.y *= inv;
        float2 p1 = unpack2(o2[i][1]); p1.x *= inv; p1.y *= inv;
        const int t = qb * 128 + 8 * ty + i;
        float* yrow = g_y + t * C_DIM + h * D_DIM;
        *(float2*)&yrow[2 * tx]      = p0;
        *(float2*)&yrow[2 * tx + 32] = p1;
    }
}

// ---------------------------------------------------------------------------
// Kernel 3: projection GEMM  y[4096,768] @ Wp[768,768] + b -> out
// ---------------------------------------------------------------------------
__global__ __launch_bounds__(256, 1)
void proj_gemm_kernel(const float* __restrict__ W,
                      const float* __restrict__ bias,
                      float* __restrict__ out) {
    const int m0 = blockIdx.y * 128;
    const int n0 = blockIdx.x * 128;
    const int tx = threadIdx.x & 15, ty = threadIdx.x >> 4;

    ull acc[8][4];
    #pragma unroll
    for (int i = 0; i < 8; i++)
        #pragma unroll
        for (int j = 0; j < 4; j++) acc[i][j] = 0ull;

    gemm_tile(g_y, C_DIM, W, C_DIM, m0, n0, C_DIM, acc);

    #pragma unroll
    for (int j = 0; j < 4; j++) {
        const int f = n0 + 2 * tx + 32 * j;
        const float b0 = bias[f], b1 = bias[f + 1];
        #pragma unroll
        for (int i = 0; i < 8; i++) {
            const int t = m0 + 8 * ty + i;
            float2 r = unpack2(acc[i][j]);
            r.x += b0; r.y += b1;
            *(float2*)&out[t * C_DIM + f] = r;
        }
    }
}

// ---------------------------------------------------------------------------
extern "C" void kernel_launch(void* const* d_in, const int* in_sizes, int n_in,
                              void* d_out, int out_size) {
    const float* x      = (const float*)d_in[0];
    // d_in[1] is the causal mask — applied analytically in attn_kernel.
    const float* W_qkv  = (const float*)d_in[2];
    const float* b_qkv  = (const float*)d_in[3];
    const float* W_proj = (const float*)d_in[4];
    const float* b_proj = (const float*)d_in[5];
    float* out = (float*)d_out;

    {   // QKV GEMM: M=4096, N=2304
        dim3 grid(C3_DIM / 128, T_DIM / 128);
        qkv_gemm_kernel<<<grid, 256>>>(x, W_qkv, b_qkv);
    }
    {   // Attention
        static int smem_set = 0;
        const int smem_bytes = (128 + 64 + 64 + 128) * AP * (int)sizeof(float);
        if (!smem_set) {
            cudaFuncSetAttribute(attn_kernel,
                                 cudaFuncAttributeMaxDynamicSharedMemorySize,
                                 smem_bytes);
            smem_set = 1;
        }
        dim3 grid(T_DIM / 128, H_DIM);
        attn_kernel<<<grid, 256, smem_bytes>>>();
    }
    {   // Projection GEMM: M=4096, N=768
        dim3 grid(C_DIM / 128, T_DIM / 128);
        proj_gemm_kernel<<<grid, 256>>>(W_proj, b_proj, out);
    }
}

// round 5
// speedup vs baseline: 6.4568x; 4.5341x over previous
#include <cuda_runtime.h>
#include <cuda_fp16.h>
#include <math.h>
#include <stdint.h>

#define T_DIM 4096
#define C_DIM 768
#define H_DIM 12
#define D_DIM 64
#define C3_DIM 2304

// ---------------------------------------------------------------------------
// Global scratch (allocation-free rule). 16B-aligned for uint4 access.
// ---------------------------------------------------------------------------
__device__ __align__(16) __half g_qh[H_DIM * T_DIM * D_DIM];
__device__ __align__(16) __half g_kh[H_DIM * T_DIM * D_DIM];
__device__ __align__(16) __half g_vh[H_DIM * T_DIM * D_DIM];
__device__ __align__(16) __half g_xh[T_DIM * C_DIM];
__device__ __align__(16) __half g_yh[T_DIM * C_DIM];
__device__ __align__(16) __half g_wqt[C3_DIM * C_DIM];   // W_qkv^T [N][K]
__device__ __align__(16) __half g_wpt[C_DIM * C_DIM];    // W_proj^T [N][K]

// ---------------------------------------------------------------------------
// PTX helpers (sm_80-level: compiles under plain sm_103 target)
// ---------------------------------------------------------------------------
__device__ __forceinline__ uint32_t smem_u32(const void* p) {
    uint32_t a;
    asm("{ .reg .u64 t; cvta.to.shared.u64 t, %1; cvt.u32.u64 %0, t; }"
        : "=r"(a) : "l"(p));
    return a;
}

#define LDSM_X4(r0, r1, r2, r3, addr) \
    asm volatile("ldmatrix.sync.aligned.m8n8.x4.shared.b16 {%0,%1,%2,%3}, [%4];" \
                 : "=r"(r0), "=r"(r1), "=r"(r2), "=r"(r3) : "r"(addr))

#define LDSM_X4T(r0, r1, r2, r3, addr) \
    asm volatile("ldmatrix.sync.aligned.m8n8.x4.trans.shared.b16 {%0,%1,%2,%3}, [%4];" \
                 : "=r"(r0), "=r"(r1), "=r"(r2), "=r"(r3) : "r"(addr))

#define MMA16816(d, a, b0, b1) \
    asm volatile("mma.sync.aligned.m16n8k16.row.col.f32.f16.f16.f32 " \
                 "{%0,%1,%2,%3}, {%4,%5,%6,%7}, {%8,%9}, {%0,%1,%2,%3};" \
                 : "+f"((d)[0]), "+f"((d)[1]), "+f"((d)[2]), "+f"((d)[3]) \
                 : "r"((a)[0]), "r"((a)[1]), "r"((a)[2]), "r"((a)[3]), \
                   "r"(b0), "r"(b1))

// pack two f32 -> f16x2 (lo = first element, hi = second)
__device__ __forceinline__ uint32_t packh2(float lo, float hi) {
    uint32_t d;
    asm("cvt.rn.f16x2.f32 %0, %1, %2;" : "=r"(d) : "f"(hi), "f"(lo));
    return d;
}

// MUFU-free exp (clamped: -1e30 -> ~0)
__device__ __forceinline__ float fast_exp(float x) {
    float t = fmaxf(x * 1.4426950408889634f, -126.0f);
    int   n = __float2int_rn(t);
    float r = t - (float)n;
    float p = 1.3333558146428443e-3f;
    p = fmaf(p, r, 9.6181291976353663e-3f);
    p = fmaf(p, r, 5.5504108664823058e-2f);
    p = fmaf(p, r, 2.4022650695910071e-1f);
    p = fmaf(p, r, 6.9314718055994531e-1f);
    p = fmaf(p, r, 1.0f);
    return p * __int_as_float((n + 127) << 23);
}

// ---------------------------------------------------------------------------
// Prepass: fp32 -> fp16 (same layout)
// ---------------------------------------------------------------------------
__global__ void convert_f16_kernel(const float* __restrict__ src,
                                   __half* __restrict__ dst, int n4) {
    int i = blockIdx.x * blockDim.x + threadIdx.x;
    if (i >= n4) return;
    float4 v = ((const float4*)src)[i];
    uint2 o;
    o.x = packh2(v.x, v.y);
    o.y = packh2(v.z, v.w);
    *(uint2*)&dst[4 * (size_t)i] = o;
}

// Prepass: fp32 [R][C] -> fp16 [C][R] (transpose)
__global__ void transpose_f16_kernel(const float* __restrict__ src,
                                     __half* __restrict__ dst, int R, int C) {
    __shared__ float t[32][33];
    const int bx = blockIdx.x * 32, by = blockIdx.y * 32;
    const int x = threadIdx.x, y = threadIdx.y;
    #pragma unroll
    for (int i = 0; i < 4; i++)
        t[y * 4 + i][x] = src[(size_t)(by + y * 4 + i) * C + bx + x];
    __syncthreads();
    #pragma unroll
    for (int i = 0; i < 4; i++)
        dst[(size_t)(bx + y * 4 + i) * R + by + x] = __float2half_rn(t[x][y * 4 + i]);
}

// ---------------------------------------------------------------------------
// fp16 mma GEMM: C[M,N] = A[M,K] @ B[N,K]^T, K=768, tile 128x128, BK=64.
// 8 warps: warp (wm 0..1, wn 0..3) -> 64x32 output. MODE 0: qkv scatter.
// ---------------------------------------------------------------------------
template <int MODE>
__global__ __launch_bounds__(256, 2)
void mma_gemm_kernel(const __half* __restrict__ A,
                     const __half* __restrict__ B,
                     const float* __restrict__ bias,
                     float* __restrict__ outp) {
    __shared__ __half As[128][72];
    __shared__ __half Bs[128][72];

    const int tid = threadIdx.x;
    const int w = tid >> 5, lane = tid & 31;
    const int wm = w >> 2, wn = w & 3;
    const int g = lane >> 2, qd = lane & 3;
    const int m0 = blockIdx.y * 128;
    const int n0 = blockIdx.x * 128;

    float acc[4][4][4];
    #pragma unroll
    for (int mt = 0; mt < 4; mt++)
        #pragma unroll
        for (int nt = 0; nt < 4; nt++)
            #pragma unroll
            for (int r = 0; r < 4; r++) acc[mt][nt][r] = 0.0f;

    // precomputed smem addrs
    uint32_t a_base[4], b_base[2];
    #pragma unroll
    for (int mt = 0; mt < 4; mt++)
        a_base[mt] = smem_u32(&As[wm * 64 + mt * 16 + (lane & 15)][(lane >> 4) * 8]);
    #pragma unroll
    for (int p = 0; p < 2; p++)
        b_base[p] = smem_u32(&Bs[wn * 32 + p * 16 + (lane >> 4) * 8 + (lane & 7)]
                                [((lane >> 3) & 1) * 8]);

    for (int c = 0; c < 12; c++) {
        const int k0 = c * 64;
        __syncthreads();   // prior chunk's ldmatrix reads complete
        #pragma unroll
        for (int i = tid; i < 1024; i += 256) {
            const int r = i >> 3, sg = i & 7;
            *(uint4*)&As[r][sg * 8] = *(const uint4*)&A[(size_t)(m0 + r) * C_DIM + k0 + sg * 8];
            *(uint4*)&Bs[r][sg * 8] = *(const uint4*)&B[(size_t)(n0 + r) * C_DIM + k0 + sg * 8];
        }
        __syncthreads();

        #pragma unroll
        for (int kt = 0; kt < 4; kt++) {
            uint32_t af[4][4];
            #pragma unroll
            for (int mt = 0; mt < 4; mt++)
                LDSM_X4(af[mt][0], af[mt][1], af[mt][2], af[mt][3],
                        a_base[mt] + kt * 32);
            #pragma unroll
            for (int p = 0; p < 2; p++) {
                uint32_t b0, b1, b2, b3;
                LDSM_X4(b0, b1, b2, b3, b_base[p] + kt * 32);
                #pragma unroll
                for (int mt = 0; mt < 4; mt++) {
                    MMA16816(acc[mt][2 * p], af[mt], b0, b1);
                    MMA16816(acc[mt][2 * p + 1], af[mt], b2, b3);
                }
            }
        }
    }

    // epilogue
    #pragma unroll
    for (int nt = 0; nt < 4; nt++) {
        const int f = n0 + wn * 32 + nt * 8 + qd * 2;
        const float b0v = bias[f], b1v = bias[f + 1];
        if (MODE == 0) {
            const int sec = f / C_DIM;
            const int cc = f - sec * C_DIM;
            const int hh = cc >> 6, d = cc & 63;
            const float sc = (sec == 0) ? 0.125f : 1.0f;
            __half* dst = (sec == 0) ? g_qh : (sec == 1) ? g_kh : g_vh;
            #pragma unroll
            for (int mt = 0; mt < 4; mt++) {
                const int m = m0 + wm * 64 + mt * 16 + g;
                *(uint32_t*)&dst[((size_t)hh * T_DIM + m) * D_DIM + d] =
                    packh2((acc[mt][nt][0] + b0v) * sc, (acc[mt][nt][1] + b1v) * sc);
                *(uint32_t*)&dst[((size_t)hh * T_DIM + m + 8) * D_DIM + d] =
                    packh2((acc[mt][nt][2] + b0v) * sc, (acc[mt][nt][3] + b1v) * sc);
            }
        } else {
            #pragma unroll
            for (int mt = 0; mt < 4; mt++) {
                const int m = m0 + wm * 64 + mt * 16 + g;
                float2 r0 = make_float2(acc[mt][nt][0] + b0v, acc[mt][nt][1] + b1v);
                float2 r1 = make_float2(acc[mt][nt][2] + b0v, acc[mt][nt][3] + b1v);
                *(float2*)&outp[(size_t)m * C_DIM + f] = r0;
                *(float2*)&outp[(size_t)(m + 8) * C_DIM + f] = r1;
            }
        }
    }
}

// ---------------------------------------------------------------------------
// Causal flash attention, fp16 mma. CTA: 128 q-rows, 8 warps (16 rows each),
// key blocks of 64. S/P/O all register-resident in mma fragment layouts.
// ---------------------------------------------------------------------------
__global__ __launch_bounds__(256)
void attn_kernel() {
    __shared__ __half Qs[128][72];
    __shared__ __half Ks[64][72];
    __shared__ __half Vs[64][72];

    const int h = blockIdx.y;
    const int qb = gridDim.x - 1 - blockIdx.x;   // heavy blocks first
    const int tid = threadIdx.x;
    const int w = tid >> 5, lane = tid & 31;
    const int g = lane >> 2, qd = lane & 3;

    // stage Q (already scaled by 1/8 at qkv epilogue)
    const __half* Qg = g_qh + ((size_t)h * T_DIM + qb * 128) * D_DIM;
    #pragma unroll
    for (int i = tid; i < 1024; i += 256) {
        const int r = i >> 3, sg = i & 7;
        *(uint4*)&Qs[r][sg * 8] = *(const uint4*)&Qg[r * D_DIM + sg * 8];
    }
    __syncthreads();

    // Q fragments (held for whole kernel): qf[kt][0..3]
    uint32_t qf[4][4];
    {
        const uint32_t qa = smem_u32(&Qs[w * 16 + (lane & 15)][(lane >> 4) * 8]);
        #pragma unroll
        for (int kt = 0; kt < 4; kt++)
            LDSM_X4(qf[kt][0], qf[kt][1], qf[kt][2], qf[kt][3], qa + kt * 32);
    }

    float o[8][4];
    #pragma unroll
    for (int nt = 0; nt < 8; nt++)
        #pragma unroll
        for (int r = 0; r < 4; r++) o[nt][r] = 0.0f;
    float m0r = -1e30f, m1r = -1e30f, l0r = 0.0f, l1r = 0.0f;

    const int row0 = qb * 128 + w * 16 + g;   // lane's first q row
    const int row1 = row0 + 8;

    const uint32_t k_base = smem_u32(&Ks[(lane >> 4) * 8 + (lane & 7)][((lane >> 3) & 1) * 8]);
    const uint32_t v_base = smem_u32(&Vs[lane & 15][(lane >> 4) * 8]);

    const int jend = 2 * qb + 1;
    for (int jb = 0; jb <= jend; jb++) {
        __syncthreads();   // prior block's ldmatrix reads complete
        const __half* Kg = g_kh + ((size_t)h * T_DIM + jb * 64) * D_DIM;
        const __half* Vg = g_vh + ((size_t)h * T_DIM + jb * 64) * D_DIM;
        #pragma unroll
        for (int i = tid; i < 512; i += 256) {
            const int r = i >> 3, sg = i & 7;
            *(uint4*)&Ks[r][sg * 8] = *(const uint4*)&Kg[r * D_DIM + sg * 8];
            *(uint4*)&Vs[r][sg * 8] = *(const uint4*)&Vg[r * D_DIM + sg * 8];
        }
        __syncthreads();

        // ---- S = Q K^T ----
        float s[8][4];
        #pragma unroll
        for (int nt = 0; nt < 8; nt++)
            #pragma unroll
            for (int r = 0; r < 4; r++) s[nt][r] = 0.0f;

        #pragma unroll
        for (int kt = 0; kt < 4; kt++) {
            #pragma unroll
            for (int p = 0; p < 4; p++) {        // 4 pairs of n8 key tiles
                uint32_t b0, b1, b2, b3;
                LDSM_X4(b0, b1, b2, b3, k_base + p * 16 * 144 + kt * 32);
                MMA16816(s[2 * p], qf[kt], b0, b1);
                MMA16816(s[2 * p + 1], qf[kt], b2, b3);
            }
        }

        // ---- causal mask (only last two key blocks can clip) ----
        if (jb >= 2 * qb) {
            #pragma unroll
            for (int nt = 0; nt < 8; nt++) {
                const int cb = jb * 64 + nt * 8 + qd * 2;
                if (cb > row0)     s[nt][0] = -1e30f;
                if (cb + 1 > row0) s[nt][1] = -1e30f;
                if (cb > row1)     s[nt][2] = -1e30f;
                if (cb + 1 > row1) s[nt][3] = -1e30f;
            }
        }

        // ---- online softmax (rows row0, row1 per lane; quad shuffles) ----
        float bm0 = s[0][0], bm1 = s[0][2];
        #pragma unroll
        for (int nt = 0; nt < 8; nt++) {
            bm0 = fmaxf(bm0, fmaxf(s[nt][0], s[nt][1]));
            bm1 = fmaxf(bm1, fmaxf(s[nt][2], s[nt][3]));
        }
        bm0 = fmaxf(bm0, __shfl_xor_sync(0xffffffffu, bm0, 1));
        bm0 = fmaxf(bm0, __shfl_xor_sync(0xffffffffu, bm0, 2));
        bm1 = fmaxf(bm1, __shfl_xor_sync(0xffffffffu, bm1, 1));
        bm1 = fmaxf(bm1, __shfl_xor_sync(0xffffffffu, bm1, 2));
        const float mn0 = fmaxf(m0r, bm0), mn1 = fmaxf(m1r, bm1);
        const float cr0 = fast_exp(m0r - mn0), cr1 = fast_exp(m1r - mn1);
        m0r = mn0; m1r = mn1;

        float rs0 = 0.0f, rs1 = 0.0f;
        #pragma unroll
        for (int nt = 0; nt < 8; nt++) {
            s[nt][0] = fast_exp(s[nt][0] - mn0); rs0 += s[nt][0];
            s[nt][1] = fast_exp(s[nt][1] - mn0); rs0 += s[nt][1];
            s[nt][2] = fast_exp(s[nt][2] - mn1); rs1 += s[nt][2];
            s[nt][3] = fast_exp(s[nt][3] - mn1); rs1 += s[nt][3];
        }
        rs0 += __shfl_xor_sync(0xffffffffu, rs0, 1);
        rs0 += __shfl_xor_sync(0xffffffffu, rs0, 2);
        rs1 += __shfl_xor_sync(0xffffffffu, rs1, 1);
        rs1 += __shfl_xor_sync(0xffffffffu, rs1, 2);
        l0r = l0r * cr0 + rs0;
        l1r = l1r * cr1 + rs1;

        #pragma unroll
        for (int nt = 0; nt < 8; nt++) {
            o[nt][0] *= cr0; o[nt][1] *= cr0;
            o[nt][2] *= cr1; o[nt][3] *= cr1;
        }

        // ---- P fragments (register cvt, no SMEM) ----
        uint32_t pf[4][4];
        #pragma unroll
        for (int kt = 0; kt < 4; kt++) {
            pf[kt][0] = packh2(s[2 * kt][0],     s[2 * kt][1]);
            pf[kt][1] = packh2(s[2 * kt][2],     s[2 * kt][3]);
            pf[kt][2] = packh2(s[2 * kt + 1][0], s[2 * kt + 1][1]);
            pf[kt][3] = packh2(s[2 * kt + 1][2], s[2 * kt + 1][3]);
        }

        // ---- O += P V ----
        #pragma unroll
        for (int kt = 0; kt < 4; kt++) {
            #pragma unroll
            for (int dt = 0; dt < 4; dt++) {
                uint32_t v0, v1, v2, v3;
                LDSM_X4T(v0, v1, v2, v3, v_base + kt * 16 * 144 + dt * 32);
                MMA16816(o[2 * dt], pf[kt], v0, v1);
                MMA16816(o[2 * dt + 1], pf[kt], v2, v3);
            }
        }
    }

    // epilogue: normalize, write y fp16 [T][C]
    const float il0 = 1.0f / l0r, il1 = 1.0f / l1r;
    __half* y0 = g_yh + (size_t)row0 * C_DIM + h * D_DIM;
    __half* y1 = g_yh + (size_t)row1 * C_DIM + h * D_DIM;
    #pragma unroll
    for (int nt = 0; nt < 8; nt++) {
        const int d = nt * 8 + qd * 2;
        *(uint32_t*)&y0[d] = packh2(o[nt][0] * il0, o[nt][1] * il0);
        *(uint32_t*)&y1[d] = packh2(o[nt][2] * il1, o[nt][3] * il1);
    }
}

// ---------------------------------------------------------------------------
extern "C" void kernel_launch(void* const* d_in, const int* in_sizes, int n_in,
                              void* d_out, int out_size) {
    const float* x      = (const float*)d_in[0];
    // d_in[1] = causal mask, applied analytically
    const float* W_qkv  = (const float*)d_in[2];
    const float* b_qkv  = (const float*)d_in[3];
    const float* W_proj = (const float*)d_in[4];
    const float* b_proj = (const float*)d_in[5];
    float* out = (float*)d_out;

    static int init_done = 0;
    static __half *xh, *wqt, *wpt, *yh;
    if (!init_done) {
        cudaGetSymbolAddress((void**)&xh,  g_xh);
        cudaGetSymbolAddress((void**)&wqt, g_wqt);
        cudaGetSymbolAddress((void**)&wpt, g_wpt);
        cudaGetSymbolAddress((void**)&yh,  g_yh);
        init_done = 1;
    }

    // prepasses
    {
        int n4 = T_DIM * C_DIM / 4;
        convert_f16_kernel<<<(n4 + 255) / 256, 256>>>(x, xh, n4);
        transpose_f16_kernel<<<dim3(C3_DIM / 32, C_DIM / 32), dim3(32, 8)>>>(
            W_qkv, wqt, C_DIM, C3_DIM);
        transpose_f16_kernel<<<dim3(C_DIM / 32, C_DIM / 32), dim3(32, 8)>>>(
            W_proj, wpt, C_DIM, C_DIM);
    }
    // QKV GEMM (tensor cores via mma.sync) -> fp16 Q(K scaled)/K/V
    mma_gemm_kernel<0><<<dim3(C3_DIM / 128, T_DIM / 128), 256>>>(
        xh, wqt, b_qkv, nullptr);
    // Attention -> fp16 y
    attn_kernel<<<dim3(T_DIM / 128, H_DIM), 256>>>();
    // Projection GEMM -> fp32 out
    mma_gemm_kernel<1><<<dim3(C_DIM / 128, T_DIM / 128), 256>>>(
        yh, wpt, b_proj, out);
}

// round 6
// speedup vs baseline: 7.5363x; 1.1672x over previous
#include <cuda_runtime.h>
#include <cuda_fp16.h>
#include <math.h>
#include <stdint.h>

#define T_DIM 4096
#define C_DIM 768
#define H_DIM 12
#define D_DIM 64
#define C3_DIM 2304

// ---------------------------------------------------------------------------
// Global scratch (allocation-free rule). 16B-aligned for uint4/cp.async.
// ---------------------------------------------------------------------------
__device__ __align__(16) __half g_qh[H_DIM * T_DIM * D_DIM];
__device__ __align__(16) __half g_kh[H_DIM * T_DIM * D_DIM];
__device__ __align__(16) __half g_vh[H_DIM * T_DIM * D_DIM];
__device__ __align__(16) __half g_xh[T_DIM * C_DIM];
__device__ __align__(16) __half g_yh[T_DIM * C_DIM];
__device__ __align__(16) __half g_wqt[C3_DIM * C_DIM];   // W_qkv^T [N][K]
__device__ __align__(16) __half g_wpt[C_DIM * C_DIM];    // W_proj^T [N][K]

// ---------------------------------------------------------------------------
// PTX helpers (sm_80-level: compile under plain sm_103 target)
// ---------------------------------------------------------------------------
__device__ __forceinline__ uint32_t smem_u32(const void* p) {
    uint32_t a;
    asm("{ .reg .u64 t; cvta.to.shared.u64 t, %1; cvt.u32.u64 %0, t; }"
        : "=r"(a) : "l"(p));
    return a;
}

#define CP16(dst, src) \
    asm volatile("cp.async.cg.shared.global [%0], [%1], 16;" \
                 :: "r"(dst), "l"(src))
#define CP_COMMIT() asm volatile("cp.async.commit_group;" ::: "memory")
#define CP_WAIT0()  asm volatile("cp.async.wait_group 0;" ::: "memory")

#define LDSM_X4(r0, r1, r2, r3, addr) \
    asm volatile("ldmatrix.sync.aligned.m8n8.x4.shared.b16 {%0,%1,%2,%3}, [%4];" \
                 : "=r"(r0), "=r"(r1), "=r"(r2), "=r"(r3) : "r"(addr))

#define LDSM_X4T(r0, r1, r2, r3, addr) \
    asm volatile("ldmatrix.sync.aligned.m8n8.x4.trans.shared.b16 {%0,%1,%2,%3}, [%4];" \
                 : "=r"(r0), "=r"(r1), "=r"(r2), "=r"(r3) : "r"(addr))

#define MMA16816(d, a, b0, b1) \
    asm volatile("mma.sync.aligned.m16n8k16.row.col.f32.f16.f16.f32 " \
                 "{%0,%1,%2,%3}, {%4,%5,%6,%7}, {%8,%9}, {%0,%1,%2,%3};" \
                 : "+f"((d)[0]), "+f"((d)[1]), "+f"((d)[2]), "+f"((d)[3]) \
                 : "r"((a)[0]), "r"((a)[1]), "r"((a)[2]), "r"((a)[3]), \
                   "r"(b0), "r"(b1))

__device__ __forceinline__ uint32_t packh2(float lo, float hi) {
    uint32_t d;
    asm("cvt.rn.f16x2.f32 %0, %1, %2;" : "=r"(d) : "f"(hi), "f"(lo));
    return d;
}

// MUFU-free exp (clamped: -1e30 -> ~0)
__device__ __forceinline__ float fast_exp(float x) {
    float t = fmaxf(x * 1.4426950408889634f, -126.0f);
    int   n = __float2int_rn(t);
    float r = t - (float)n;
    float p = 1.3333558146428443e-3f;
    p = fmaf(p, r, 9.6181291976353663e-3f);
    p = fmaf(p, r, 5.5504108664823058e-2f);
    p = fmaf(p, r, 2.4022650695910071e-1f);
    p = fmaf(p, r, 6.9314718055994531e-1f);
    p = fmaf(p, r, 1.0f);
    return p * __int_as_float((n + 127) << 23);
}

// ---------------------------------------------------------------------------
// Prepasses
// ---------------------------------------------------------------------------
__global__ void convert_f16_kernel(const float* __restrict__ src,
                                   __half* __restrict__ dst, int n4) {
    int i = blockIdx.x * blockDim.x + threadIdx.x;
    if (i >= n4) return;
    float4 v = ((const float4*)src)[i];
    uint2 o;
    o.x = packh2(v.x, v.y);
    o.y = packh2(v.z, v.w);
    *(uint2*)&dst[4 * (size_t)i] = o;
}

__global__ void transpose_f16_kernel(const float* __restrict__ src,
                                     __half* __restrict__ dst, int R, int C) {
    __shared__ float t[32][33];
    const int bx = blockIdx.x * 32, by = blockIdx.y * 32;
    const int x = threadIdx.x, y = threadIdx.y;
    #pragma unroll
    for (int i = 0; i < 4; i++)
        t[y * 4 + i][x] = src[(size_t)(by + y * 4 + i) * C + bx + x];
    __syncthreads();
    #pragma unroll
    for (int i = 0; i < 4; i++)
        dst[(size_t)(bx + y * 4 + i) * R + by + x] = __float2half_rn(t[x][y * 4 + i]);
}

// ---------------------------------------------------------------------------
// fp16 mma GEMM, cp.async double-buffered. C[M,N] = A[M,K] @ B[N,K]^T.
// Tile 128x128, BK=64, 8 warps (64x32 each). MODE 0: qkv scatter to Q/K/V.
// ---------------------------------------------------------------------------
#define GEMM_BUF (128 * 72)             // halves per As/Bs buffer
#define GEMM_BUF_B (GEMM_BUF * 2)       // bytes
#define GEMM_SMEM_BYTES (4 * GEMM_BUF * 2)

template <int MODE>
__global__ __launch_bounds__(256, 2)
void mma_gemm_kernel(const __half* __restrict__ A,
                     const __half* __restrict__ B,
                     const float* __restrict__ bias,
                     float* __restrict__ outp) {
    extern __shared__ __half sm[];
    __half (*As)[128][72] = (__half(*)[128][72])sm;
    __half (*Bs)[128][72] = (__half(*)[128][72])(sm + 2 * GEMM_BUF);

    const int tid = threadIdx.x;
    const int w = tid >> 5, lane = tid & 31;
    const int wm = w >> 2, wn = w & 3;
    const int g = lane >> 2, qd = lane & 3;
    const int m0 = blockIdx.y * 128;
    const int n0 = blockIdx.x * 128;

    float acc[4][4][4];
    #pragma unroll
    for (int mt = 0; mt < 4; mt++)
        #pragma unroll
        for (int nt = 0; nt < 4; nt++)
            #pragma unroll
            for (int r = 0; r < 4; r++) acc[mt][nt][r] = 0.0f;

    // prologue: stage chunk 0
    #pragma unroll
    for (int i = tid; i < 1024; i += 256) {
        const int r = i >> 3, sg = i & 7;
        CP16(smem_u32(&As[0][r][sg * 8]), &A[(size_t)(m0 + r) * C_DIM + sg * 8]);
        CP16(smem_u32(&Bs[0][r][sg * 8]), &B[(size_t)(n0 + r) * C_DIM + sg * 8]);
    }
    CP_COMMIT();

    uint32_t a_base[4], b_base[2];
    #pragma unroll
    for (int mt = 0; mt < 4; mt++)
        a_base[mt] = smem_u32(&As[0][wm * 64 + mt * 16 + (lane & 15)][(lane >> 4) * 8]);
    #pragma unroll
    for (int p = 0; p < 2; p++)
        b_base[p] = smem_u32(&Bs[0][wn * 32 + p * 16 + (lane >> 4) * 8 + (lane & 7)]
                                [((lane >> 3) & 1) * 8]);

    for (int c = 0; c < 12; c++) {
        CP_WAIT0();
        __syncthreads();
        if (c < 11) {
            const int k0 = (c + 1) * 64;
            const int nb = (c + 1) & 1;
            #pragma unroll
            for (int i = tid; i < 1024; i += 256) {
                const int r = i >> 3, sg = i & 7;
                CP16(smem_u32(&As[nb][r][sg * 8]),
                     &A[(size_t)(m0 + r) * C_DIM + k0 + sg * 8]);
                CP16(smem_u32(&Bs[nb][r][sg * 8]),
                     &B[(size_t)(n0 + r) * C_DIM + k0 + sg * 8]);
            }
            CP_COMMIT();
        }
        const uint32_t boff = (uint32_t)(c & 1) * GEMM_BUF_B;
        #pragma unroll
        for (int kt = 0; kt < 4; kt++) {
            uint32_t af[4][4];
            #pragma unroll
            for (int mt = 0; mt < 4; mt++)
                LDSM_X4(af[mt][0], af[mt][1], af[mt][2], af[mt][3],
                        a_base[mt] + boff + kt * 32);
            #pragma unroll
            for (int p = 0; p < 2; p++) {
                uint32_t b0, b1, b2, b3;
                LDSM_X4(b0, b1, b2, b3, b_base[p] + boff + kt * 32);
                #pragma unroll
                for (int mt = 0; mt < 4; mt++) {
                    MMA16816(acc[mt][2 * p], af[mt], b0, b1);
                    MMA16816(acc[mt][2 * p + 1], af[mt], b2, b3);
                }
            }
        }
    }

    // epilogue
    #pragma unroll
    for (int nt = 0; nt < 4; nt++) {
        const int f = n0 + wn * 32 + nt * 8 + qd * 2;
        const float b0v = bias[f], b1v = bias[f + 1];
        if (MODE == 0) {
            const int sec = f / C_DIM;
            const int cc = f - sec * C_DIM;
            const int hh = cc >> 6, d = cc & 63;
            const float sc = (sec == 0) ? 0.125f : 1.0f;
            __half* dst = (sec == 0) ? g_qh : (sec == 1) ? g_kh : g_vh;
            #pragma unroll
            for (int mt = 0; mt < 4; mt++) {
                const int m = m0 + wm * 64 + mt * 16 + g;
                *(uint32_t*)&dst[((size_t)hh * T_DIM + m) * D_DIM + d] =
                    packh2((acc[mt][nt][0] + b0v) * sc, (acc[mt][nt][1] + b1v) * sc);
                *(uint32_t*)&dst[((size_t)hh * T_DIM + m + 8) * D_DIM + d] =
                    packh2((acc[mt][nt][2] + b0v) * sc, (acc[mt][nt][3] + b1v) * sc);
            }
        } else {
            #pragma unroll
            for (int mt = 0; mt < 4; mt++) {
                const int m = m0 + wm * 64 + mt * 16 + g;
                float2 r0 = make_float2(acc[mt][nt][0] + b0v, acc[mt][nt][1] + b1v);
                float2 r1 = make_float2(acc[mt][nt][2] + b0v, acc[mt][nt][3] + b1v);
                *(float2*)&outp[(size_t)m * C_DIM + f] = r0;
                *(float2*)&outp[(size_t)(m + 8) * C_DIM + f] = r1;
            }
        }
    }
}

// ---------------------------------------------------------------------------
// Causal flash attention, fp16 mma, cp.async double-buffered K/V.
// CTA: 128 q-rows, 8 warps (16 rows each), key blocks of 64.
// ---------------------------------------------------------------------------
#define KV_BUF (64 * 72)                // halves per K/V buffer
#define KV_BUF_B (KV_BUF * 2)           // bytes
#define ATTN_SMEM_BYTES ((128 * 72 + 4 * KV_BUF) * 2)

__global__ __launch_bounds__(256, 2)
void attn_kernel() {
    extern __shared__ __half sm[];
    __half (*Qs)[72] = (__half(*)[72])sm;                          // [128][72]
    __half (*Ks)[64][72] = (__half(*)[64][72])(sm + 128 * 72);
    __half (*Vs)[64][72] = (__half(*)[64][72])(sm + 128 * 72 + 2 * KV_BUF);

    const int h = blockIdx.y;
    const int qb = gridDim.x - 1 - blockIdx.x;   // heavy blocks first
    const int tid = threadIdx.x;
    const int w = tid >> 5, lane = tid & 31;
    const int g = lane >> 2, qd = lane & 3;

    // stage Q + K/V block 0 as one async group
    const __half* Qg = g_qh + ((size_t)h * T_DIM + qb * 128) * D_DIM;
    #pragma unroll
    for (int i = tid; i < 1024; i += 256) {
        const int r = i >> 3, sg = i & 7;
        CP16(smem_u32(&Qs[r][sg * 8]), &Qg[r * D_DIM + sg * 8]);
    }
    {
        const __half* Kg = g_kh + ((size_t)h * T_DIM) * D_DIM + (size_t)0;
        const __half* Vg = g_vh + ((size_t)h * T_DIM) * D_DIM + (size_t)0;
        #pragma unroll
        for (int i = tid; i < 512; i += 256) {
            const int r = i >> 3, sg = i & 7;
            CP16(smem_u32(&Ks[0][r][sg * 8]), &Kg[r * D_DIM + sg * 8]);
            CP16(smem_u32(&Vs[0][r][sg * 8]), &Vg[r * D_DIM + sg * 8]);
        }
    }
    CP_COMMIT();

    uint32_t qf[4][4];
    float o[8][4];
    #pragma unroll
    for (int nt = 0; nt < 8; nt++)
        #pragma unroll
        for (int r = 0; r < 4; r++) o[nt][r] = 0.0f;
    float m0r = -1e30f, m1r = -1e30f, l0r = 0.0f, l1r = 0.0f;

    const int row0 = qb * 128 + w * 16 + g;
    const int row1 = row0 + 8;

    const uint32_t k_base = smem_u32(&Ks[0][(lane >> 4) * 8 + (lane & 7)][((lane >> 3) & 1) * 8]);
    const uint32_t v_base = smem_u32(&Vs[0][lane & 15][(lane >> 4) * 8]);

    const int jend = 2 * qb + 1;
    for (int jb = 0; jb <= jend; jb++) {
        CP_WAIT0();
        __syncthreads();
        if (jb == 0) {
            const uint32_t qa = smem_u32(&Qs[w * 16 + (lane & 15)][(lane >> 4) * 8]);
            #pragma unroll
            for (int kt = 0; kt < 4; kt++)
                LDSM_X4(qf[kt][0], qf[kt][1], qf[kt][2], qf[kt][3], qa + kt * 32);
        }
        if (jb < jend) {
            const int nb = (jb + 1) & 1;
            const __half* Kg = g_kh + ((size_t)h * T_DIM + (jb + 1) * 64) * D_DIM;
            const __half* Vg = g_vh + ((size_t)h * T_DIM + (jb + 1) * 64) * D_DIM;
            #pragma unroll
            for (int i = tid; i < 512; i += 256) {
                const int r = i >> 3, sg = i & 7;
                CP16(smem_u32(&Ks[nb][r][sg * 8]), &Kg[r * D_DIM + sg * 8]);
                CP16(smem_u32(&Vs[nb][r][sg * 8]), &Vg[r * D_DIM + sg * 8]);
            }
            CP_COMMIT();
        }
        const uint32_t boff = (uint32_t)(jb & 1) * KV_BUF_B;

        // ---- S = Q K^T ----
        float s[8][4];
        #pragma unroll
        for (int nt = 0; nt < 8; nt++)
            #pragma unroll
            for (int r = 0; r < 4; r++) s[nt][r] = 0.0f;

        #pragma unroll
        for (int kt = 0; kt < 4; kt++) {
            #pragma unroll
            for (int p = 0; p < 4; p++) {
                uint32_t b0, b1, b2, b3;
                LDSM_X4(b0, b1, b2, b3, k_base + boff + p * 16 * 144 + kt * 32);
                MMA16816(s[2 * p], qf[kt], b0, b1);
                MMA16816(s[2 * p + 1], qf[kt], b2, b3);
            }
        }

        // ---- causal mask (only last two key blocks can clip) ----
        if (jb >= 2 * qb) {
            #pragma unroll
            for (int nt = 0; nt < 8; nt++) {
                const int cb = jb * 64 + nt * 8 + qd * 2;
                if (cb > row0)     s[nt][0] = -1e30f;
                if (cb + 1 > row0) s[nt][1] = -1e30f;
                if (cb > row1)     s[nt][2] = -1e30f;
                if (cb + 1 > row1) s[nt][3] = -1e30f;
            }
        }

        // ---- online softmax ----
        float bm0 = s[0][0], bm1 = s[0][2];
        #pragma unroll
        for (int nt = 0; nt < 8; nt++) {
            bm0 = fmaxf(bm0, fmaxf(s[nt][0], s[nt][1]));
            bm1 = fmaxf(bm1, fmaxf(s[nt][2], s[nt][3]));
        }
        bm0 = fmaxf(bm0, __shfl_xor_sync(0xffffffffu, bm0, 1));
        bm0 = fmaxf(bm0, __shfl_xor_sync(0xffffffffu, bm0, 2));
        bm1 = fmaxf(bm1, __shfl_xor_sync(0xffffffffu, bm1, 1));
        bm1 = fmaxf(bm1, __shfl_xor_sync(0xffffffffu, bm1, 2));
        const float mn0 = fmaxf(m0r, bm0), mn1 = fmaxf(m1r, bm1);
        const float cr0 = fast_exp(m0r - mn0), cr1 = fast_exp(m1r - mn1);
        m0r = mn0; m1r = mn1;

        float rs0 = 0.0f, rs1 = 0.0f;
        #pragma unroll
        for (int nt = 0; nt < 8; nt++) {
            s[nt][0] = fast_exp(s[nt][0] - mn0); rs0 += s[nt][0];
            s[nt][1] = fast_exp(s[nt][1] - mn0); rs0 += s[nt][1];
            s[nt][2] = fast_exp(s[nt][2] - mn1); rs1 += s[nt][2];
            s[nt][3] = fast_exp(s[nt][3] - mn1); rs1 += s[nt][3];
        }
        rs0 += __shfl_xor_sync(0xffffffffu, rs0, 1);
        rs0 += __shfl_xor_sync(0xffffffffu, rs0, 2);
        rs1 += __shfl_xor_sync(0xffffffffu, rs1, 1);
        rs1 += __shfl_xor_sync(0xffffffffu, rs1, 2);
        l0r = l0r * cr0 + rs0;
        l1r = l1r * cr1 + rs1;

        #pragma unroll
        for (int nt = 0; nt < 8; nt++) {
            o[nt][0] *= cr0; o[nt][1] *= cr0;
            o[nt][2] *= cr1; o[nt][3] *= cr1;
        }

        // ---- P fragments (register cvt, no SMEM) ----
        uint32_t pf[4][4];
        #pragma unroll
        for (int kt = 0; kt < 4; kt++) {
            pf[kt][0] = packh2(s[2 * kt][0],     s[2 * kt][1]);
            pf[kt][1] = packh2(s[2 * kt][2],     s[2 * kt][3]);
            pf[kt][2] = packh2(s[2 * kt + 1][0], s[2 * kt + 1][1]);
            pf[kt][3] = packh2(s[2 * kt + 1][2], s[2 * kt + 1][3]);
        }

        // ---- O += P V ----
        #pragma unroll
        for (int kt = 0; kt < 4; kt++) {
            #pragma unroll
            for (int dt = 0; dt < 4; dt++) {
                uint32_t v0, v1, v2, v3;
                LDSM_X4T(v0, v1, v2, v3, v_base + boff + kt * 16 * 144 + dt * 32);
                MMA16816(o[2 * dt], pf[kt], v0, v1);
                MMA16816(o[2 * dt + 1], pf[kt], v2, v3);
            }
        }
    }

    // epilogue: normalize, write y fp16 [T][C]
    const float il0 = 1.0f / l0r, il1 = 1.0f / l1r;
    __half* y0 = g_yh + (size_t)row0 * C_DIM + h * D_DIM;
    __half* y1 = g_yh + (size_t)row1 * C_DIM + h * D_DIM;
    #pragma unroll
    for (int nt = 0; nt < 8; nt++) {
        const int d = nt * 8 + qd * 2;
        *(uint32_t*)&y0[d] = packh2(o[nt][0] * il0, o[nt][1] * il0);
        *(uint32_t*)&y1[d] = packh2(o[nt][2] * il1, o[nt][3] * il1);
    }
}

// ---------------------------------------------------------------------------
extern "C" void kernel_launch(void* const* d_in, const int* in_sizes, int n_in,
                              void* d_out, int out_size) {
    const float* x      = (const float*)d_in[0];
    // d_in[1] = causal mask, applied analytically
    const float* W_qkv  = (const float*)d_in[2];
    const float* b_qkv  = (const float*)d_in[3];
    const float* W_proj = (const float*)d_in[4];
    const float* b_proj = (const float*)d_in[5];
    float* out = (float*)d_out;

    static int init_done = 0;
    static __half *xh, *wqt, *wpt, *yh;
    if (!init_done) {
        cudaGetSymbolAddress((void**)&xh,  g_xh);
        cudaGetSymbolAddress((void**)&wqt, g_wqt);
        cudaGetSymbolAddress((void**)&wpt, g_wpt);
        cudaGetSymbolAddress((void**)&yh,  g_yh);
        cudaFuncSetAttribute(mma_gemm_kernel<0>,
                             cudaFuncAttributeMaxDynamicSharedMemorySize,
                             GEMM_SMEM_BYTES);
        cudaFuncSetAttribute(mma_gemm_kernel<1>,
                             cudaFuncAttributeMaxDynamicSharedMemorySize,
                             GEMM_SMEM_BYTES);
        cudaFuncSetAttribute(attn_kernel,
                             cudaFuncAttributeMaxDynamicSharedMemorySize,
                             ATTN_SMEM_BYTES);
        init_done = 1;
    }

    // prepasses
    {
        int n4 = T_DIM * C_DIM / 4;
        convert_f16_kernel<<<(n4 + 255) / 256, 256>>>(x, xh, n4);
        transpose_f16_kernel<<<dim3(C3_DIM / 32, C_DIM / 32), dim3(32, 8)>>>(
            W_qkv, wqt, C_DIM, C3_DIM);
        transpose_f16_kernel<<<dim3(C_DIM / 32, C_DIM / 32), dim3(32, 8)>>>(
            W_proj, wpt, C_DIM, C_DIM);
    }
    // QKV GEMM -> fp16 Q(scaled)/K/V
    mma_gemm_kernel<0><<<dim3(C3_DIM / 128, T_DIM / 128), 256, GEMM_SMEM_BYTES>>>(
        xh, wqt, b_qkv, nullptr);
    // Attention -> fp16 y
    attn_kernel<<<dim3(T_DIM / 128, H_DIM), 256, ATTN_SMEM_BYTES>>>();
    // Projection GEMM -> fp32 out
    mma_gemm_kernel<1><<<dim3(C_DIM / 128, T_DIM / 128), 256, GEMM_SMEM_BYTES>>>(
        yh, wpt, b_proj, out);
}

// round 7
// speedup vs baseline: 10.0027x; 1.3273x over previous
#include <cuda_runtime.h>
#include <cuda_fp16.h>
#include <math.h>
#include <stdint.h>

#define T_DIM 4096
#define C_DIM 768
#define H_DIM 12
#define D_DIM 64
#define C3_DIM 2304

// ---------------------------------------------------------------------------
// Global scratch (allocation-free rule). 16B-aligned for uint4/cp.async.
// ---------------------------------------------------------------------------
__device__ __align__(16) __half g_qh[H_DIM * T_DIM * D_DIM];
__device__ __align__(16) __half g_kh[H_DIM * T_DIM * D_DIM];
__device__ __align__(16) __half g_vh[H_DIM * T_DIM * D_DIM];
__device__ __align__(16) __half g_xh[T_DIM * C_DIM];
__device__ __align__(16) __half g_yh[T_DIM * C_DIM];
__device__ __align__(16) __half g_wqt[C3_DIM * C_DIM];   // W_qkv^T [N][K]
__device__ __align__(16) __half g_wpt[C_DIM * C_DIM];    // W_proj^T [N][K]

// ---------------------------------------------------------------------------
// PTX helpers (sm_80-level: compile under plain sm_103 target)
// ---------------------------------------------------------------------------
__device__ __forceinline__ uint32_t smem_u32(const void* p) {
    uint32_t a;
    asm("{ .reg .u64 t; cvta.to.shared.u64 t, %1; cvt.u32.u64 %0, t; }"
        : "=r"(a) : "l"(p));
    return a;
}

#define CP16(dst, src) \
    asm volatile("cp.async.cg.shared.global [%0], [%1], 16;" \
                 :: "r"(dst), "l"(src))
#define CP_COMMIT() asm volatile("cp.async.commit_group;" ::: "memory")
#define CP_WAIT0()  asm volatile("cp.async.wait_group 0;" ::: "memory")

#define LDSM_X4(r0, r1, r2, r3, addr) \
    asm volatile("ldmatrix.sync.aligned.m8n8.x4.shared.b16 {%0,%1,%2,%3}, [%4];" \
                 : "=r"(r0), "=r"(r1), "=r"(r2), "=r"(r3) : "r"(addr))

#define LDSM_X4T(r0, r1, r2, r3, addr) \
    asm volatile("ldmatrix.sync.aligned.m8n8.x4.trans.shared.b16 {%0,%1,%2,%3}, [%4];" \
                 : "=r"(r0), "=r"(r1), "=r"(r2), "=r"(r3) : "r"(addr))

#define MMA16816(d, a, b0, b1) \
    asm volatile("mma.sync.aligned.m16n8k16.row.col.f32.f16.f16.f32 " \
                 "{%0,%1,%2,%3}, {%4,%5,%6,%7}, {%8,%9}, {%0,%1,%2,%3};" \
                 : "+f"((d)[0]), "+f"((d)[1]), "+f"((d)[2]), "+f"((d)[3]) \
                 : "r"((a)[0]), "r"((a)[1]), "r"((a)[2]), "r"((a)[3]), \
                   "r"(b0), "r"(b1))

__device__ __forceinline__ uint32_t packh2(float lo, float hi) {
    uint32_t d;
    asm("cvt.rn.f16x2.f32 %0, %1, %2;" : "=r"(d) : "f"(hi), "f"(lo));
    return d;
}

// MUFU exp2 — 1 issue slot, runs on the otherwise-idle MUFU pipe.
// ftz: ex2(-1e30) -> 0, so masked lanes vanish without a clamp.
__device__ __forceinline__ float ex2(float x) {
    float y;
    asm("ex2.approx.ftz.f32 %0, %1;" : "=f"(y) : "f"(x));
    return y;
}

// ---------------------------------------------------------------------------
// Prepasses
// ---------------------------------------------------------------------------
__global__ void convert_f16_kernel(const float* __restrict__ src,
                                   __half* __restrict__ dst, int n4) {
    int i = blockIdx.x * blockDim.x + threadIdx.x;
    if (i >= n4) return;
    float4 v = ((const float4*)src)[i];
    uint2 o;
    o.x = packh2(v.x, v.y);
    o.y = packh2(v.z, v.w);
    *(uint2*)&dst[4 * (size_t)i] = o;
}

__global__ void transpose_f16_kernel(const float* __restrict__ src,
                                     __half* __restrict__ dst, int R, int C) {
    __shared__ float t[32][33];
    const int bx = blockIdx.x * 32, by = blockIdx.y * 32;
    const int x = threadIdx.x, y = threadIdx.y;
    #pragma unroll
    for (int i = 0; i < 4; i++)
        t[y * 4 + i][x] = src[(size_t)(by + y * 4 + i) * C + bx + x];
    __syncthreads();
    #pragma unroll
    for (int i = 0; i < 4; i++)
        dst[(size_t)(bx + y * 4 + i) * R + by + x] = __float2half_rn(t[x][y * 4 + i]);
}

// ---------------------------------------------------------------------------
// fp16 mma GEMM, cp.async double-buffered. C[M,N] = A[M,K] @ B[N,K]^T.
// Tile 128x128, BK=64, 8 warps (64x32 each). MODE 0: qkv scatter to Q/K/V.
// Q is pre-scaled by 0.125*log2(e) so attention softmax works in log2 domain.
// ---------------------------------------------------------------------------
#define GEMM_BUF (128 * 72)             // halves per As/Bs buffer
#define GEMM_BUF_B (GEMM_BUF * 2)       // bytes
#define GEMM_SMEM_BYTES (4 * GEMM_BUF * 2)

#define Q_SCALE 0.18033688011112042f    // 0.125 * log2(e)

template <int MODE>
__global__ __launch_bounds__(256, 2)
void mma_gemm_kernel(const __half* __restrict__ A,
                     const __half* __restrict__ B,
                     const float* __restrict__ bias,
                     float* __restrict__ outp) {
    extern __shared__ __half sm[];
    __half (*As)[128][72] = (__half(*)[128][72])sm;
    __half (*Bs)[128][72] = (__half(*)[128][72])(sm + 2 * GEMM_BUF);

    const int tid = threadIdx.x;
    const int w = tid >> 5, lane = tid & 31;
    const int wm = w >> 2, wn = w & 3;
    const int g = lane >> 2, qd = lane & 3;
    const int m0 = blockIdx.y * 128;
    const int n0 = blockIdx.x * 128;

    float acc[4][4][4];
    #pragma unroll
    for (int mt = 0; mt < 4; mt++)
        #pragma unroll
        for (int nt = 0; nt < 4; nt++)
            #pragma unroll
            for (int r = 0; r < 4; r++) acc[mt][nt][r] = 0.0f;

    // prologue: stage chunk 0
    #pragma unroll
    for (int i = tid; i < 1024; i += 256) {
        const int r = i >> 3, sg = i & 7;
        CP16(smem_u32(&As[0][r][sg * 8]), &A[(size_t)(m0 + r) * C_DIM + sg * 8]);
        CP16(smem_u32(&Bs[0][r][sg * 8]), &B[(size_t)(n0 + r) * C_DIM + sg * 8]);
    }
    CP_COMMIT();

    uint32_t a_base[4], b_base[2];
    #pragma unroll
    for (int mt = 0; mt < 4; mt++)
        a_base[mt] = smem_u32(&As[0][wm * 64 + mt * 16 + (lane & 15)][(lane >> 4) * 8]);
    #pragma unroll
    for (int p = 0; p < 2; p++)
        b_base[p] = smem_u32(&Bs[0][wn * 32 + p * 16 + (lane >> 4) * 8 + (lane & 7)]
                                [((lane >> 3) & 1) * 8]);

    for (int c = 0; c < 12; c++) {
        CP_WAIT0();
        __syncthreads();
        if (c < 11) {
            const int k0 = (c + 1) * 64;
            const int nb = (c + 1) & 1;
            #pragma unroll
            for (int i = tid; i < 1024; i += 256) {
                const int r = i >> 3, sg = i & 7;
                CP16(smem_u32(&As[nb][r][sg * 8]),
                     &A[(size_t)(m0 + r) * C_DIM + k0 + sg * 8]);
                CP16(smem_u32(&Bs[nb][r][sg * 8]),
                     &B[(size_t)(n0 + r) * C_DIM + k0 + sg * 8]);
            }
            CP_COMMIT();
        }
        const uint32_t boff = (uint32_t)(c & 1) * GEMM_BUF_B;
        #pragma unroll
        for (int kt = 0; kt < 4; kt++) {
            uint32_t af[4][4];
            #pragma unroll
            for (int mt = 0; mt < 4; mt++)
                LDSM_X4(af[mt][0], af[mt][1], af[mt][2], af[mt][3],
                        a_base[mt] + boff + kt * 32);
            #pragma unroll
            for (int p = 0; p < 2; p++) {
                uint32_t b0, b1, b2, b3;
                LDSM_X4(b0, b1, b2, b3, b_base[p] + boff + kt * 32);
                #pragma unroll
                for (int mt = 0; mt < 4; mt++) {
                    MMA16816(acc[mt][2 * p], af[mt], b0, b1);
                    MMA16816(acc[mt][2 * p + 1], af[mt], b2, b3);
                }
            }
        }
    }

    // epilogue
    #pragma unroll
    for (int nt = 0; nt < 4; nt++) {
        const int f = n0 + wn * 32 + nt * 8 + qd * 2;
        const float b0v = bias[f], b1v = bias[f + 1];
        if (MODE == 0) {
            const int sec = f / C_DIM;
            const int cc = f - sec * C_DIM;
            const int hh = cc >> 6, d = cc & 63;
            const float sc = (sec == 0) ? Q_SCALE : 1.0f;
            __half* dst = (sec == 0) ? g_qh : (sec == 1) ? g_kh : g_vh;
            #pragma unroll
            for (int mt = 0; mt < 4; mt++) {
                const int m = m0 + wm * 64 + mt * 16 + g;
                *(uint32_t*)&dst[((size_t)hh * T_DIM + m) * D_DIM + d] =
                    packh2((acc[mt][nt][0] + b0v) * sc, (acc[mt][nt][1] + b1v) * sc);
                *(uint32_t*)&dst[((size_t)hh * T_DIM + m + 8) * D_DIM + d] =
                    packh2((acc[mt][nt][2] + b0v) * sc, (acc[mt][nt][3] + b1v) * sc);
            }
        } else {
            #pragma unroll
            for (int mt = 0; mt < 4; mt++) {
                const int m = m0 + wm * 64 + mt * 16 + g;
                float2 r0 = make_float2(acc[mt][nt][0] + b0v, acc[mt][nt][1] + b1v);
                float2 r1 = make_float2(acc[mt][nt][2] + b0v, acc[mt][nt][3] + b1v);
                *(float2*)&outp[(size_t)m * C_DIM + f] = r0;
                *(float2*)&outp[(size_t)(m + 8) * C_DIM + f] = r1;
            }
        }
    }
}

// ---------------------------------------------------------------------------
// Causal flash attention, fp16 mma, cp.async double-buffered K/V.
// CTA: 128 q-rows, 8 warps (16 rows each), key blocks of 64.
// Softmax in log2 domain (Q pre-scaled); exp via MUFU ex2.approx.
// ---------------------------------------------------------------------------
#define KV_BUF (64 * 72)                // halves per K/V buffer
#define KV_BUF_B (KV_BUF * 2)           // bytes
#define ATTN_SMEM_BYTES ((128 * 72 + 4 * KV_BUF) * 2)

__global__ __launch_bounds__(256, 2)
void attn_kernel() {
    extern __shared__ __half sm[];
    __half (*Qs)[72] = (__half(*)[72])sm;                          // [128][72]
    __half (*Ks)[64][72] = (__half(*)[64][72])(sm + 128 * 72);
    __half (*Vs)[64][72] = (__half(*)[64][72])(sm + 128 * 72 + 2 * KV_BUF);

    const int h = blockIdx.y;
    const int qb = gridDim.x - 1 - blockIdx.x;   // heavy blocks first
    const int tid = threadIdx.x;
    const int w = tid >> 5, lane = tid & 31;
    const int g = lane >> 2, qd = lane & 3;

    // stage Q + K/V block 0 as one async group
    const __half* Qg = g_qh + ((size_t)h * T_DIM + qb * 128) * D_DIM;
    #pragma unroll
    for (int i = tid; i < 1024; i += 256) {
        const int r = i >> 3, sg = i & 7;
        CP16(smem_u32(&Qs[r][sg * 8]), &Qg[r * D_DIM + sg * 8]);
    }
    {
        const __half* Kg = g_kh + ((size_t)h * T_DIM) * D_DIM;
        const __half* Vg = g_vh + ((size_t)h * T_DIM) * D_DIM;
        #pragma unroll
        for (int i = tid; i < 512; i += 256) {
            const int r = i >> 3, sg = i & 7;
            CP16(smem_u32(&Ks[0][r][sg * 8]), &Kg[r * D_DIM + sg * 8]);
            CP16(smem_u32(&Vs[0][r][sg * 8]), &Vg[r * D_DIM + sg * 8]);
        }
    }
    CP_COMMIT();

    uint32_t qf[4][4];
    float o[8][4];
    #pragma unroll
    for (int nt = 0; nt < 8; nt++)
        #pragma unroll
        for (int r = 0; r < 4; r++) o[nt][r] = 0.0f;
    float m0r = -1e30f, m1r = -1e30f, l0r = 0.0f, l1r = 0.0f;

    const int row0 = qb * 128 + w * 16 + g;
    const int row1 = row0 + 8;

    const uint32_t k_base = smem_u32(&Ks[0][(lane >> 4) * 8 + (lane & 7)][((lane >> 3) & 1) * 8]);
    const uint32_t v_base = smem_u32(&Vs[0][lane & 15][(lane >> 4) * 8]);

    const int jend = 2 * qb + 1;
    for (int jb = 0; jb <= jend; jb++) {
        CP_WAIT0();
        __syncthreads();
        if (jb == 0) {
            const uint32_t qa = smem_u32(&Qs[w * 16 + (lane & 15)][(lane >> 4) * 8]);
            #pragma unroll
            for (int kt = 0; kt < 4; kt++)
                LDSM_X4(qf[kt][0], qf[kt][1], qf[kt][2], qf[kt][3], qa + kt * 32);
        }
        if (jb < jend) {
            const int nb = (jb + 1) & 1;
            const __half* Kg = g_kh + ((size_t)h * T_DIM + (jb + 1) * 64) * D_DIM;
            const __half* Vg = g_vh + ((size_t)h * T_DIM + (jb + 1) * 64) * D_DIM;
            #pragma unroll
            for (int i = tid; i < 512; i += 256) {
                const int r = i >> 3, sg = i & 7;
                CP16(smem_u32(&Ks[nb][r][sg * 8]), &Kg[r * D_DIM + sg * 8]);
                CP16(smem_u32(&Vs[nb][r][sg * 8]), &Vg[r * D_DIM + sg * 8]);
            }
            CP_COMMIT();
        }
        const uint32_t boff = (uint32_t)(jb & 1) * KV_BUF_B;

        // ---- S = Q K^T (log2-domain scores; Q pre-scaled) ----
        float s[8][4];
        #pragma unroll
        for (int nt = 0; nt < 8; nt++)
            #pragma unroll
            for (int r = 0; r < 4; r++) s[nt][r] = 0.0f;

        #pragma unroll
        for (int kt = 0; kt < 4; kt++) {
            #pragma unroll
            for (int p = 0; p < 4; p++) {
                uint32_t b0, b1, b2, b3;
                LDSM_X4(b0, b1, b2, b3, k_base + boff + p * 16 * 144 + kt * 32);
                MMA16816(s[2 * p], qf[kt], b0, b1);
                MMA16816(s[2 * p + 1], qf[kt], b2, b3);
            }
        }

        // ---- causal mask (only last two key blocks can clip) ----
        if (jb >= 2 * qb) {
            #pragma unroll
            for (int nt = 0; nt < 8; nt++) {
                const int cb = jb * 64 + nt * 8 + qd * 2;
                if (cb > row0)     s[nt][0] = -1e30f;
                if (cb + 1 > row0) s[nt][1] = -1e30f;
                if (cb > row1)     s[nt][2] = -1e30f;
                if (cb + 1 > row1) s[nt][3] = -1e30f;
            }
        }

        // ---- online softmax (MUFU ex2; 2 rows per lane; quad shuffles) ----
        float bm0 = s[0][0], bm1 = s[0][2];
        #pragma unroll
        for (int nt = 0; nt < 8; nt++) {
            bm0 = fmaxf(bm0, fmaxf(s[nt][0], s[nt][1]));
            bm1 = fmaxf(bm1, fmaxf(s[nt][2], s[nt][3]));
        }
        bm0 = fmaxf(bm0, __shfl_xor_sync(0xffffffffu, bm0, 1));
        bm0 = fmaxf(bm0, __shfl_xor_sync(0xffffffffu, bm0, 2));
        bm1 = fmaxf(bm1, __shfl_xor_sync(0xffffffffu, bm1, 1));
        bm1 = fmaxf(bm1, __shfl_xor_sync(0xffffffffu, bm1, 2));
        const float mn0 = fmaxf(m0r, bm0), mn1 = fmaxf(m1r, bm1);
        const float cr0 = ex2(m0r - mn0), cr1 = ex2(m1r - mn1);
        m0r = mn0; m1r = mn1;

        float rs0 = 0.0f, rs1 = 0.0f;
        #pragma unroll
        for (int nt = 0; nt < 8; nt++) {
            s[nt][0] = ex2(s[nt][0] - mn0); rs0 += s[nt][0];
            s[nt][1] = ex2(s[nt][1] - mn0); rs0 += s[nt][1];
            s[nt][2] = ex2(s[nt][2] - mn1); rs1 += s[nt][2];
            s[nt][3] = ex2(s[nt][3] - mn1); rs1 += s[nt][3];
        }
        rs0 += __shfl_xor_sync(0xffffffffu, rs0, 1);
        rs0 += __shfl_xor_sync(0xffffffffu, rs0, 2);
        rs1 += __shfl_xor_sync(0xffffffffu, rs1, 1);
        rs1 += __shfl_xor_sync(0xffffffffu, rs1, 2);
        l0r = l0r * cr0 + rs0;
        l1r = l1r * cr1 + rs1;

        #pragma unroll
        for (int nt = 0; nt < 8; nt++) {
            o[nt][0] *= cr0; o[nt][1] *= cr0;
            o[nt][2] *= cr1; o[nt][3] *= cr1;
        }

        // ---- P fragments (register cvt, no SMEM) ----
        uint32_t pf[4][4];
        #pragma unroll
        for (int kt = 0; kt < 4; kt++) {
            pf[kt][0] = packh2(s[2 * kt][0],     s[2 * kt][1]);
            pf[kt][1] = packh2(s[2 * kt][2],     s[2 * kt][3]);
            pf[kt][2] = packh2(s[2 * kt + 1][0], s[2 * kt + 1][1]);
            pf[kt][3] = packh2(s[2 * kt + 1][2], s[2 * kt + 1][3]);
        }

        // ---- O += P V ----
        #pragma unroll
        for (int kt = 0; kt < 4; kt++) {
            #pragma unroll
            for (int dt = 0; dt < 4; dt++) {
                uint32_t v0, v1, v2, v3;
                LDSM_X4T(v0, v1, v2, v3, v_base + boff + kt * 16 * 144 + dt * 32);
                MMA16816(o[2 * dt], pf[kt], v0, v1);
                MMA16816(o[2 * dt + 1], pf[kt], v2, v3);
            }
        }
    }

    // epilogue: normalize, write y fp16 [T][C]
    const float il0 = 1.0f / l0r, il1 = 1.0f / l1r;
    __half* y0 = g_yh + (size_t)row0 * C_DIM + h * D_DIM;
    __half* y1 = g_yh + (size_t)row1 * C_DIM + h * D_DIM;
    #pragma unroll
    for (int nt = 0; nt < 8; nt++) {
        const int d = nt * 8 + qd * 2;
        *(uint32_t*)&y0[d] = packh2(o[nt][0] * il0, o[nt][1] * il0);
        *(uint32_t*)&y1[d] = packh2(o[nt][2] * il1, o[nt][3] * il1);
    }
}

// ---------------------------------------------------------------------------
extern "C" void kernel_launch(void* const* d_in, const int* in_sizes, int n_in,
                              void* d_out, int out_size) {
    const float* x      = (const float*)d_in[0];
    // d_in[1] = causal mask, applied analytically
    const float* W_qkv  = (const float*)d_in[2];
    const float* b_qkv  = (const float*)d_in[3];
    const float* W_proj = (const float*)d_in[4];
    const float* b_proj = (const float*)d_in[5];
    float* out = (float*)d_out;

    static int init_done = 0;
    static __half *xh, *wqt, *wpt, *yh;
    if (!init_done) {
        cudaGetSymbolAddress((void**)&xh,  g_xh);
        cudaGetSymbolAddress((void**)&wqt, g_wqt);
        cudaGetSymbolAddress((void**)&wpt, g_wpt);
        cudaGetSymbolAddress((void**)&yh,  g_yh);
        cudaFuncSetAttribute(mma_gemm_kernel<0>,
                             cudaFuncAttributeMaxDynamicSharedMemorySize,
                             GEMM_SMEM_BYTES);
        cudaFuncSetAttribute(mma_gemm_kernel<1>,
                             cudaFuncAttributeMaxDynamicSharedMemorySize,
                             GEMM_SMEM_BYTES);
        cudaFuncSetAttribute(attn_kernel,
                             cudaFuncAttributeMaxDynamicSharedMemorySize,
                             ATTN_SMEM_BYTES);
        init_done = 1;
    }

    // prepasses
    {
        int n4 = T_DIM * C_DIM / 4;
        convert_f16_kernel<<<(n4 + 255) / 256, 256>>>(x, xh, n4);
        transpose_f16_kernel<<<dim3(C3_DIM / 32, C_DIM / 32), dim3(32, 8)>>>(
            W_qkv, wqt, C_DIM, C3_DIM);
        transpose_f16_kernel<<<dim3(C_DIM / 32, C_DIM / 32), dim3(32, 8)>>>(
            W_proj, wpt, C_DIM, C_DIM);
    }
    // QKV GEMM -> fp16 Q(log2-scaled)/K/V
    mma_gemm_kernel<0><<<dim3(C3_DIM / 128, T_DIM / 128), 256, GEMM_SMEM_BYTES>>>(
        xh, wqt, b_qkv, nullptr);
    // Attention -> fp16 y
    attn_kernel<<<dim3(T_DIM / 128, H_DIM), 256, ATTN_SMEM_BYTES>>>();
    // Projection GEMM -> fp32 out
    mma_gemm_kernel<1><<<dim3(C_DIM / 128, T_DIM / 128), 256, GEMM_SMEM_BYTES>>>(
        yh, wpt, b_proj, out);
}

// round 8
// speedup vs baseline: 10.4266x; 1.0424x over previous
#include <cuda_runtime.h>
#include <cuda_fp16.h>
#include <math.h>
#include <stdint.h>

#define T_DIM 4096
#define C_DIM 768
#define H_DIM 12
#define D_DIM 64
#define C3_DIM 2304

// ---------------------------------------------------------------------------
// Global scratch (allocation-free rule). 16B-aligned for uint4/cp.async.
// ---------------------------------------------------------------------------
__device__ __align__(16) __half g_qh[H_DIM * T_DIM * D_DIM];
__device__ __align__(16) __half g_kh[H_DIM * T_DIM * D_DIM];
__device__ __align__(16) __half g_vh[H_DIM * T_DIM * D_DIM];
__device__ __align__(16) __half g_xh[T_DIM * C_DIM];
__device__ __align__(16) __half g_yh[T_DIM * C_DIM];
__device__ __align__(16) __half g_wq[C_DIM * C3_DIM];    // W_qkv fp16 [K][N]
__device__ __align__(16) __half g_wp[C_DIM * C_DIM];     // W_proj fp16 [K][N]

// ---------------------------------------------------------------------------
// PTX helpers (sm_80-level: compile under plain sm_103 target)
// ---------------------------------------------------------------------------
__device__ __forceinline__ uint32_t smem_u32(const void* p) {
    uint32_t a;
    asm("{ .reg .u64 t; cvta.to.shared.u64 t, %1; cvt.u32.u64 %0, t; }"
        : "=r"(a) : "l"(p));
    return a;
}

#define CP16(dst, src) \
    asm volatile("cp.async.cg.shared.global [%0], [%1], 16;" \
                 :: "r"(dst), "l"(src))
#define CP_COMMIT() asm volatile("cp.async.commit_group;" ::: "memory")
#define CP_WAIT0()  asm volatile("cp.async.wait_group 0;" ::: "memory")

#define LDSM_X4(r0, r1, r2, r3, addr) \
    asm volatile("ldmatrix.sync.aligned.m8n8.x4.shared.b16 {%0,%1,%2,%3}, [%4];" \
                 : "=r"(r0), "=r"(r1), "=r"(r2), "=r"(r3) : "r"(addr))

#define LDSM_X4T(r0, r1, r2, r3, addr) \
    asm volatile("ldmatrix.sync.aligned.m8n8.x4.trans.shared.b16 {%0,%1,%2,%3}, [%4];" \
                 : "=r"(r0), "=r"(r1), "=r"(r2), "=r"(r3) : "r"(addr))

#define MMA16816(d, a, b0, b1) \
    asm volatile("mma.sync.aligned.m16n8k16.row.col.f32.f16.f16.f32 " \
                 "{%0,%1,%2,%3}, {%4,%5,%6,%7}, {%8,%9}, {%0,%1,%2,%3};" \
                 : "+f"((d)[0]), "+f"((d)[1]), "+f"((d)[2]), "+f"((d)[3]) \
                 : "r"((a)[0]), "r"((a)[1]), "r"((a)[2]), "r"((a)[3]), \
                   "r"(b0), "r"(b1))

__device__ __forceinline__ uint32_t packh2(float lo, float hi) {
    uint32_t d;
    asm("cvt.rn.f16x2.f32 %0, %1, %2;" : "=r"(d) : "f"(hi), "f"(lo));
    return d;
}
__device__ __forceinline__ uint32_t sub2(uint32_t a, uint32_t b) {
    uint32_t d;
    asm("sub.f16x2 %0, %1, %2;" : "=r"(d) : "r"(a), "r"(b));
    return d;
}
__device__ __forceinline__ uint32_t ex2h2(uint32_t a) {
    uint32_t d;
    asm("ex2.approx.f16x2 %0, %1;" : "=r"(d) : "r"(a));
    return d;
}
__device__ __forceinline__ float ex2(float x) {
    float y;
    asm("ex2.approx.ftz.f32 %0, %1;" : "=f"(y) : "f"(x));
    return y;
}

// ---------------------------------------------------------------------------
// Prepass: fp32 -> fp16 (same layout)
// ---------------------------------------------------------------------------
__global__ void convert_f16_kernel(const float* __restrict__ src,
                                   __half* __restrict__ dst, int n4) {
    int i = blockIdx.x * blockDim.x + threadIdx.x;
    if (i >= n4) return;
    float4 v = ((const float4*)src)[i];
    uint2 o;
    o.x = packh2(v.x, v.y);
    o.y = packh2(v.z, v.w);
    *(uint2*)&dst[4 * (size_t)i] = o;
}

// ---------------------------------------------------------------------------
// fp16 mma GEMM. C[M,N] = A[M,K] @ B[K,N] (B row-major, trans-ldmatrix).
// Tile 128x128, BK=64, 8 warps (64x32 each), cp.async double-buffered.
// MODE 0: qkv scatter (Q pre-scaled by 0.125*log2e). MODE 1: fp32 out.
// ---------------------------------------------------------------------------
#define GA_BUF (128 * 72)               // halves per A buffer
#define GB_BUF (64 * 136)               // halves per B buffer
#define GA_BUF_B (GA_BUF * 2)
#define GB_BUF_B (GB_BUF * 2)
#define GEMM_SMEM_BYTES ((2 * GA_BUF + 2 * GB_BUF) * 2)

#define Q_SCALE 0.18033688011112042f    // 0.125 * log2(e)

template <int MODE>
__global__ __launch_bounds__(256, 2)
void mma_gemm_kernel(const __half* __restrict__ A,
                     const __half* __restrict__ B, int ldb,
                     const float* __restrict__ bias,
                     float* __restrict__ outp) {
    extern __shared__ __half sm[];
    __half (*As)[128][72] = (__half(*)[128][72])sm;
    __half (*Bs)[64][136] = (__half(*)[64][136])(sm + 2 * GA_BUF);

    const int tid = threadIdx.x;
    const int w = tid >> 5, lane = tid & 31;
    const int wm = w >> 2, wn = w & 3;
    const int g = lane >> 2, qd = lane & 3;
    const int m0 = blockIdx.y * 128;
    const int n0 = blockIdx.x * 128;

    float acc[4][4][4];
    #pragma unroll
    for (int mt = 0; mt < 4; mt++)
        #pragma unroll
        for (int nt = 0; nt < 4; nt++)
            #pragma unroll
            for (int r = 0; r < 4; r++) acc[mt][nt][r] = 0.0f;

    // prologue: stage chunk 0
    #pragma unroll
    for (int i = tid; i < 1024; i += 256) {
        const int ra = i >> 3, sga = i & 7;
        CP16(smem_u32(&As[0][ra][sga * 8]),
             &A[(size_t)(m0 + ra) * C_DIM + sga * 8]);
        const int rb = i >> 4, sgb = i & 15;
        CP16(smem_u32(&Bs[0][rb][sgb * 8]),
             &B[(size_t)rb * ldb + n0 + sgb * 8]);
    }
    CP_COMMIT();

    uint32_t a_base[4];
    #pragma unroll
    for (int mt = 0; mt < 4; mt++)
        a_base[mt] = smem_u32(&As[0][wm * 64 + mt * 16 + (lane & 15)][(lane >> 4) * 8]);
    const uint32_t b_base = smem_u32(&Bs[0][lane & 15][wn * 32 + (lane >> 4) * 8]);

    for (int c = 0; c < 12; c++) {
        CP_WAIT0();
        __syncthreads();
        if (c < 11) {
            const int k0 = (c + 1) * 64;
            const int nb = (c + 1) & 1;
            #pragma unroll
            for (int i = tid; i < 1024; i += 256) {
                const int ra = i >> 3, sga = i & 7;
                CP16(smem_u32(&As[nb][ra][sga * 8]),
                     &A[(size_t)(m0 + ra) * C_DIM + k0 + sga * 8]);
                const int rb = i >> 4, sgb = i & 15;
                CP16(smem_u32(&Bs[nb][rb][sgb * 8]),
                     &B[(size_t)(k0 + rb) * ldb + n0 + sgb * 8]);
            }
            CP_COMMIT();
        }
        const uint32_t boffA = (uint32_t)(c & 1) * GA_BUF_B;
        const uint32_t boffB = (uint32_t)(c & 1) * GB_BUF_B;
        #pragma unroll
        for (int kt = 0; kt < 4; kt++) {
            uint32_t af[4][4];
            #pragma unroll
            for (int mt = 0; mt < 4; mt++)
                LDSM_X4(af[mt][0], af[mt][1], af[mt][2], af[mt][3],
                        a_base[mt] + boffA + kt * 32);
            #pragma unroll
            for (int p = 0; p < 2; p++) {
                uint32_t b0, b1, b2, b3;
                LDSM_X4T(b0, b1, b2, b3,
                         b_base + boffB + kt * (16 * 272) + p * 32);
                #pragma unroll
                for (int mt = 0; mt < 4; mt++) {
                    MMA16816(acc[mt][2 * p], af[mt], b0, b1);
                    MMA16816(acc[mt][2 * p + 1], af[mt], b2, b3);
                }
            }
        }
    }

    // epilogue
    #pragma unroll
    for (int nt = 0; nt < 4; nt++) {
        const int f = n0 + wn * 32 + nt * 8 + qd * 2;
        const float b0v = bias[f], b1v = bias[f + 1];
        if (MODE == 0) {
            const int sec = f / C_DIM;
            const int cc = f - sec * C_DIM;
            const int hh = cc >> 6, d = cc & 63;
            const float sc = (sec == 0) ? Q_SCALE : 1.0f;
            __half* dst = (sec == 0) ? g_qh : (sec == 1) ? g_kh : g_vh;
            #pragma unroll
            for (int mt = 0; mt < 4; mt++) {
                const int m = m0 + wm * 64 + mt * 16 + g;
                *(uint32_t*)&dst[((size_t)hh * T_DIM + m) * D_DIM + d] =
                    packh2((acc[mt][nt][0] + b0v) * sc, (acc[mt][nt][1] + b1v) * sc);
                *(uint32_t*)&dst[((size_t)hh * T_DIM + m + 8) * D_DIM + d] =
                    packh2((acc[mt][nt][2] + b0v) * sc, (acc[mt][nt][3] + b1v) * sc);
            }
        } else {
            #pragma unroll
            for (int mt = 0; mt < 4; mt++) {
                const int m = m0 + wm * 64 + mt * 16 + g;
                float2 r0 = make_float2(acc[mt][nt][0] + b0v, acc[mt][nt][1] + b1v);
                float2 r1 = make_float2(acc[mt][nt][2] + b0v, acc[mt][nt][3] + b1v);
                *(float2*)&outp[(size_t)m * C_DIM + f] = r0;
                *(float2*)&outp[(size_t)(m + 8) * C_DIM + f] = r1;
            }
        }
    }
}

// ---------------------------------------------------------------------------
// Causal flash attention, fp16 mma, cp.async double-buffered K/V.
// CTA: 128 q-rows, 8 warps (16 rows each), key blocks of 64.
// Softmax in log2 domain; f16x2 sub+ex2 writes P fragments directly;
// row-sum l computed by an extra ones-column MMA (no adds/shuffles).
// ---------------------------------------------------------------------------
#define KV_BUF (64 * 72)
#define KV_BUF_B (KV_BUF * 2)
#define ATTN_SMEM_BYTES ((128 * 72 + 4 * KV_BUF) * 2)
#define ONES_H2 0x3C003C00u             // (1.0h, 1.0h)

__global__ __launch_bounds__(256, 2)
void attn_kernel() {
    extern __shared__ __half sm[];
    __half (*Qs)[72] = (__half(*)[72])sm;
    __half (*Ks)[64][72] = (__half(*)[64][72])(sm + 128 * 72);
    __half (*Vs)[64][72] = (__half(*)[64][72])(sm + 128 * 72 + 2 * KV_BUF);

    const int h = blockIdx.y;
    const int qb = gridDim.x - 1 - blockIdx.x;   // heavy blocks first
    const int tid = threadIdx.x;
    const int w = tid >> 5, lane = tid & 31;
    const int g = lane >> 2, qd = lane & 3;

    // stage Q + K/V block 0 as one async group
    const __half* Qg = g_qh + ((size_t)h * T_DIM + qb * 128) * D_DIM;
    #pragma unroll
    for (int i = tid; i < 1024; i += 256) {
        const int r = i >> 3, sg = i & 7;
        CP16(smem_u32(&Qs[r][sg * 8]), &Qg[r * D_DIM + sg * 8]);
    }
    {
        const __half* Kg = g_kh + ((size_t)h * T_DIM) * D_DIM;
        const __half* Vg = g_vh + ((size_t)h * T_DIM) * D_DIM;
        #pragma unroll
        for (int i = tid; i < 512; i += 256) {
            const int r = i >> 3, sg = i & 7;
            CP16(smem_u32(&Ks[0][r][sg * 8]), &Kg[r * D_DIM + sg * 8]);
            CP16(smem_u32(&Vs[0][r][sg * 8]), &Vg[r * D_DIM + sg * 8]);
        }
    }
    CP_COMMIT();

    uint32_t qf[4][4];
    float o[8][4];
    float lsum[4] = {0.0f, 0.0f, 0.0f, 0.0f};
    #pragma unroll
    for (int nt = 0; nt < 8; nt++)
        #pragma unroll
        for (int r = 0; r < 4; r++) o[nt][r] = 0.0f;
    float m0r = -1e30f, m1r = -1e30f;

    const int row0 = qb * 128 + w * 16 + g;
    const int row1 = row0 + 8;

    const uint32_t k_base = smem_u32(&Ks[0][(lane >> 4) * 8 + (lane & 7)][((lane >> 3) & 1) * 8]);
    const uint32_t v_base = smem_u32(&Vs[0][lane & 15][(lane >> 4) * 8]);

    const int jend = 2 * qb + 1;
    for (int jb = 0; jb <= jend; jb++) {
        CP_WAIT0();
        __syncthreads();
        if (jb == 0) {
            const uint32_t qa = smem_u32(&Qs[w * 16 + (lane & 15)][(lane >> 4) * 8]);
            #pragma unroll
            for (int kt = 0; kt < 4; kt++)
                LDSM_X4(qf[kt][0], qf[kt][1], qf[kt][2], qf[kt][3], qa + kt * 32);
        }
        if (jb < jend) {
            const int nb = (jb + 1) & 1;
            const __half* Kg = g_kh + ((size_t)h * T_DIM + (jb + 1) * 64) * D_DIM;
            const __half* Vg = g_vh + ((size_t)h * T_DIM + (jb + 1) * 64) * D_DIM;
            #pragma unroll
            for (int i = tid; i < 512; i += 256) {
                const int r = i >> 3, sg = i & 7;
                CP16(smem_u32(&Ks[nb][r][sg * 8]), &Kg[r * D_DIM + sg * 8]);
                CP16(smem_u32(&Vs[nb][r][sg * 8]), &Vg[r * D_DIM + sg * 8]);
            }
            CP_COMMIT();
        }
        const uint32_t boff = (uint32_t)(jb & 1) * KV_BUF_B;

        // ---- S = Q K^T (log2-domain scores) ----
        float s[8][4];
        #pragma unroll
        for (int nt = 0; nt < 8; nt++)
            #pragma unroll
            for (int r = 0; r < 4; r++) s[nt][r] = 0.0f;

        #pragma unroll
        for (int kt = 0; kt < 4; kt++) {
            #pragma unroll
            for (int p = 0; p < 4; p++) {
                uint32_t b0, b1, b2, b3;
                LDSM_X4(b0, b1, b2, b3, k_base + boff + p * 16 * 144 + kt * 32);
                MMA16816(s[2 * p], qf[kt], b0, b1);
                MMA16816(s[2 * p + 1], qf[kt], b2, b3);
            }
        }

        // ---- causal mask ----
        if (jb >= 2 * qb) {
            #pragma unroll
            for (int nt = 0; nt < 8; nt++) {
                const int cb = jb * 64 + nt * 8 + qd * 2;
                if (cb > row0)     s[nt][0] = -1e30f;
                if (cb + 1 > row0) s[nt][1] = -1e30f;
                if (cb > row1)     s[nt][2] = -1e30f;
                if (cb + 1 > row1) s[nt][3] = -1e30f;
            }
        }

        // ---- row max (f32, quad shuffles) ----
        float bm0 = s[0][0], bm1 = s[0][2];
        #pragma unroll
        for (int nt = 0; nt < 8; nt++) {
            bm0 = fmaxf(bm0, fmaxf(s[nt][0], s[nt][1]));
            bm1 = fmaxf(bm1, fmaxf(s[nt][2], s[nt][3]));
        }
        bm0 = fmaxf(bm0, __shfl_xor_sync(0xffffffffu, bm0, 1));
        bm0 = fmaxf(bm0, __shfl_xor_sync(0xffffffffu, bm0, 2));
        bm1 = fmaxf(bm1, __shfl_xor_sync(0xffffffffu, bm1, 1));
        bm1 = fmaxf(bm1, __shfl_xor_sync(0xffffffffu, bm1, 2));
        const float mn0 = fmaxf(m0r, bm0), mn1 = fmaxf(m1r, bm1);
        const float cr0 = ex2(m0r - mn0), cr1 = ex2(m1r - mn1);
        m0r = mn0; m1r = mn1;

        // rescale O and l accumulators
        #pragma unroll
        for (int nt = 0; nt < 8; nt++) {
            o[nt][0] *= cr0; o[nt][1] *= cr0;
            o[nt][2] *= cr1; o[nt][3] *= cr1;
        }
        lsum[0] *= cr0; lsum[1] *= cr0;
        lsum[2] *= cr1; lsum[3] *= cr1;

        // ---- P fragments: f16x2 sub + MUFU ex2.f16x2, straight to mma-A ----
        const uint32_t mh0 = packh2(mn0, mn0);
        const uint32_t mh1 = packh2(mn1, mn1);
        uint32_t pf[4][4];
        #pragma unroll
        for (int kt = 0; kt < 4; kt++) {
            pf[kt][0] = ex2h2(sub2(packh2(s[2 * kt][0],     s[2 * kt][1]),     mh0));
            pf[kt][1] = ex2h2(sub2(packh2(s[2 * kt][2],     s[2 * kt][3]),     mh1));
            pf[kt][2] = ex2h2(sub2(packh2(s[2 * kt + 1][0], s[2 * kt + 1][1]), mh0));
            pf[kt][3] = ex2h2(sub2(packh2(s[2 * kt + 1][2], s[2 * kt + 1][3]), mh1));
        }

        // ---- O += P V, and l += P ones (extra n8 MMA; all cols = row sum) ----
        #pragma unroll
        for (int kt = 0; kt < 4; kt++) {
            MMA16816(lsum, pf[kt], ONES_H2, ONES_H2);
            #pragma unroll
            for (int dt = 0; dt < 4; dt++) {
                uint32_t v0, v1, v2, v3;
                LDSM_X4T(v0, v1, v2, v3, v_base + boff + kt * 16 * 144 + dt * 32);
                MMA16816(o[2 * dt], pf[kt], v0, v1);
                MMA16816(o[2 * dt + 1], pf[kt], v2, v3);
            }
        }
    }

    // epilogue: normalize, write y fp16 [T][C]
    const float il0 = 1.0f / lsum[0], il1 = 1.0f / lsum[2];
    __half* y0 = g_yh + (size_t)row0 * C_DIM + h * D_DIM;
    __half* y1 = g_yh + (size_t)row1 * C_DIM + h * D_DIM;
    #pragma unroll
    for (int nt = 0; nt < 8; nt++) {
        const int d = nt * 8 + qd * 2;
        *(uint32_t*)&y0[d] = packh2(o[nt][0] * il0, o[nt][1] * il0);
        *(uint32_t*)&y1[d] = packh2(o[nt][2] * il1, o[nt][3] * il1);
    }
}

// ---------------------------------------------------------------------------
extern "C" void kernel_launch(void* const* d_in, const int* in_sizes, int n_in,
                              void* d_out, int out_size) {
    const float* x      = (const float*)d_in[0];
    // d_in[1] = causal mask, applied analytically
    const float* W_qkv  = (const float*)d_in[2];
    const float* b_qkv  = (const float*)d_in[3];
    const float* W_proj = (const float*)d_in[4];
    const float* b_proj = (const float*)d_in[5];
    float* out = (float*)d_out;

    static int init_done = 0;
    static __half *xh, *wq, *wp, *yh;
    if (!init_done) {
        cudaGetSymbolAddress((void**)&xh, g_xh);
        cudaGetSymbolAddress((void**)&wq, g_wq);
        cudaGetSymbolAddress((void**)&wp, g_wp);
        cudaGetSymbolAddress((void**)&yh, g_yh);
        cudaFuncSetAttribute(mma_gemm_kernel<0>,
                             cudaFuncAttributeMaxDynamicSharedMemorySize,
                             GEMM_SMEM_BYTES);
        cudaFuncSetAttribute(mma_gemm_kernel<1>,
                             cudaFuncAttributeMaxDynamicSharedMemorySize,
                             GEMM_SMEM_BYTES);
        cudaFuncSetAttribute(attn_kernel,
                             cudaFuncAttributeMaxDynamicSharedMemorySize,
                             ATTN_SMEM_BYTES);
        init_done = 1;
    }

    // prepasses: straight fp32->fp16 converts (no transposes)
    convert_f16_kernel<<<(T_DIM * C_DIM / 4 + 255) / 256, 256>>>(
        x, xh, T_DIM * C_DIM / 4);
    convert_f16_kernel<<<(C_DIM * C3_DIM / 4 + 255) / 256, 256>>>(
        W_qkv, wq, C_DIM * C3_DIM / 4);
    convert_f16_kernel<<<(C_DIM * C_DIM / 4 + 255) / 256, 256>>>(
        W_proj, wp, C_DIM * C_DIM / 4);

    // QKV GEMM -> fp16 Q(log2-scaled)/K/V
    mma_gemm_kernel<0><<<dim3(C3_DIM / 128, T_DIM / 128), 256, GEMM_SMEM_BYTES>>>(
        xh, wq, C3_DIM, b_qkv, nullptr);
    // Attention -> fp16 y
    attn_kernel<<<dim3(T_DIM / 128, H_DIM), 256, ATTN_SMEM_BYTES>>>();
    // Projection GEMM -> fp32 out
    mma_gemm_kernel<1><<<dim3(C_DIM / 128, T_DIM / 128), 256, GEMM_SMEM_BYTES>>>(
        yh, wp, C_DIM, b_proj, out);
}